// round 2
// baseline (speedup 1.0000x reference)
#include <cuda_runtime.h>

#define T_  4096
#define B_  8
#define D_  512
#define L_  128
#define H_  8
#define DH  64
#define LH  16
#define M_  (B_*T_)     // 32768 rows
#define NCH 32          // chunks over T
#define CSZ 128         // chunk size (T_/NCH)

// ---- scratch (static device globals: allowed; runtime allocs are not) ----
__device__ float g_Q[M_*L_];        // Q raw -> qs_pre -> w   (in-place stages)
__device__ float g_K[M_*L_];        // K_exp
__device__ float g_V[M_*D_];        // V
__device__ float g_y[M_*D_];        // scan output, natural (b,t,h,dh) layout
__device__ float g_yp[M_*D_];       // permuted (= y.transpose(3,0,1,2).reshape)
__device__ float g_csum[B_*NCH*L_]; // alpha chunk prefix
__device__ float g_S[B_*H_*NCH*LH*DH]; // state chunk sums -> exclusive prefix

// ============================================================
// Tiled SGEMM: C[M,N] = A[M,K] @ B[K,N], row-major, fp32.
// 128x128 tile, BK=8, 256 threads, 8x8 microtile.
// EPI==1: C = exp(0.125 * (A@B))   (K_exp epilogue)
// Assumes M%128==0, N%128==0, K%8==0 (true for all our shapes).
// ============================================================
template<int EPI>
__global__ __launch_bounds__(256) void sgemm(const float* __restrict__ A,
                                             const float* __restrict__ Bm,
                                             float* __restrict__ C,
                                             int M, int N, int K)
{
    __shared__ float As[8][128];
    __shared__ float Bs[8][128];
    const int tid = threadIdx.x;
    const int m0 = blockIdx.y * 128;
    const int n0 = blockIdx.x * 128;
    const int tx = tid & 15, ty = tid >> 4;

    float acc[8][8];
#pragma unroll
    for (int i = 0; i < 8; i++)
#pragma unroll
        for (int j = 0; j < 8; j++) acc[i][j] = 0.f;

    const int arow = tid >> 1, ac4 = (tid & 1) * 4;
    const int brow = tid >> 5, bc4 = (tid & 31) * 4;
    const float* Ap = A + (m0 + arow) * K + ac4;
    const float* Bp = Bm + brow * N + n0 + bc4;

    for (int k0 = 0; k0 < K; k0 += 8) {
        float4 av = *(const float4*)(Ap + k0);
        float4 bv = *(const float4*)(Bp + (size_t)k0 * N);
        As[ac4 + 0][arow] = av.x;
        As[ac4 + 1][arow] = av.y;
        As[ac4 + 2][arow] = av.z;
        As[ac4 + 3][arow] = av.w;
        *(float4*)&Bs[brow][bc4] = bv;
        __syncthreads();
#pragma unroll
        for (int kk = 0; kk < 8; kk++) {
            float4 a0 = *(const float4*)&As[kk][ty * 8];
            float4 a1 = *(const float4*)&As[kk][ty * 8 + 4];
            float4 b0 = *(const float4*)&Bs[kk][tx * 8];
            float4 b1 = *(const float4*)&Bs[kk][tx * 8 + 4];
            float a[8] = {a0.x, a0.y, a0.z, a0.w, a1.x, a1.y, a1.z, a1.w};
            float b[8] = {b0.x, b0.y, b0.z, b0.w, b1.x, b1.y, b1.z, b1.w};
#pragma unroll
            for (int i = 0; i < 8; i++)
#pragma unroll
                for (int j = 0; j < 8; j++) acc[i][j] = fmaf(a[i], b[j], acc[i][j]);
        }
        __syncthreads();
    }

#pragma unroll
    for (int i = 0; i < 8; i++) {
        int row = m0 + ty * 8 + i;
        float* cp = C + (size_t)row * N + n0 + tx * 8;
        float o[8];
#pragma unroll
        for (int j = 0; j < 8; j++)
            o[j] = EPI ? __expf(0.125f * acc[i][j]) : acc[i][j];
        *(float4*)cp       = make_float4(o[0], o[1], o[2], o[3]);
        *(float4*)(cp + 4) = make_float4(o[4], o[5], o[6], o[7]);
    }
}

// ============================================================
// softmax over Lh=16 per (b,t,h); g_Q in-place: raw Q -> qs_pre
// ============================================================
__global__ void softmax_kernel()
{
    int bt = blockIdx.x;
    int l = threadIdx.x;                 // 128 threads = full L row
    int idx = bt * L_ + l;
    float q = g_Q[idx] * 0.125f;
    float m = q;
#pragma unroll
    for (int s = 8; s >= 1; s >>= 1)
        m = fmaxf(m, __shfl_xor_sync(0xffffffffu, m, s));
    float e = __expf(q - m);
    float sum = e;
#pragma unroll
    for (int s = 8; s >= 1; s >>= 1)
        sum += __shfl_xor_sync(0xffffffffu, sum, s);
    g_Q[idx] = e / sum;
}

// ============================================================
// alpha = cumsum_t(K_exp), then w = qs_pre / alpha (g_Q in-place)
// 3-pass chunked scan over T; rows are (b, l).
// ============================================================
__global__ void alpha_p1()
{
    int chunk = blockIdx.x, b = blockIdx.y, l = threadIdx.x;
    float s = 0.f;
    int base = (b * T_ + chunk * CSZ) * L_ + l;
    for (int i = 0; i < CSZ; i++) s += g_K[base + i * L_];
    g_csum[(b * NCH + chunk) * L_ + l] = s;
}
__global__ void alpha_p2()
{
    int b = blockIdx.x, l = threadIdx.x;
    float run = 0.f;
    for (int c = 0; c < NCH; c++) {
        int idx = (b * NCH + c) * L_ + l;
        float v = g_csum[idx];
        g_csum[idx] = run;          // exclusive prefix
        run += v;
    }
}
__global__ void alpha_p3()
{
    int chunk = blockIdx.x, b = blockIdx.y, l = threadIdx.x;
    float a = g_csum[(b * NCH + chunk) * L_ + l];
    int base = (b * T_ + chunk * CSZ) * L_ + l;
    for (int i = 0; i < CSZ; i++) {
        int idx = base + i * L_;
        a += g_K[idx];                       // inclusive alpha
        g_Q[idx] = __fdividef(g_Q[idx], a);  // w = qs_pre / alpha
    }
}

// ============================================================
// scan pass 1: per-(b,h,chunk) state contribution S = Ke^T @ V (16x64)
// ============================================================
__global__ __launch_bounds__(128) void state_p1()
{
    int chunk = blockIdx.x, h = blockIdx.y, b = blockIdx.z;
    int tid = threadIdx.x;
    int l = tid >> 3, d0 = (tid & 7) * 8;
    __shared__ float ke_s[16][16];
    __shared__ float v_s[16][64];
    float acc[8] = {0, 0, 0, 0, 0, 0, 0, 0};
    int t0 = chunk * CSZ;
    for (int tt = 0; tt < CSZ; tt += 16) {
#pragma unroll
        for (int r = 0; r < 2; r++) {
            int f = r * 128 + tid, tr = f >> 4, li = f & 15;
            ke_s[tr][li] = g_K[(b * T_ + t0 + tt + tr) * L_ + h * LH + li];
        }
#pragma unroll
        for (int r = 0; r < 2; r++) {
            int f = r * 128 + tid, tr = f >> 4, dq = f & 15;
            *(float4*)&v_s[tr][dq * 4] =
                *(const float4*)&g_V[(b * T_ + t0 + tt + tr) * D_ + h * DH + dq * 4];
        }
        __syncthreads();
#pragma unroll
        for (int k = 0; k < 16; k++) {
            float kl = ke_s[k][l];
            float4 va = *(const float4*)&v_s[k][d0];
            float4 vb = *(const float4*)&v_s[k][d0 + 4];
            acc[0] = fmaf(kl, va.x, acc[0]); acc[1] = fmaf(kl, va.y, acc[1]);
            acc[2] = fmaf(kl, va.z, acc[2]); acc[3] = fmaf(kl, va.w, acc[3]);
            acc[4] = fmaf(kl, vb.x, acc[4]); acc[5] = fmaf(kl, vb.y, acc[5]);
            acc[6] = fmaf(kl, vb.z, acc[6]); acc[7] = fmaf(kl, vb.w, acc[7]);
        }
        __syncthreads();
    }
    float* Sp = &g_S[(((b * H_ + h) * NCH + chunk) * LH + l) * DH + d0];
    *(float4*)Sp       = make_float4(acc[0], acc[1], acc[2], acc[3]);
    *(float4*)(Sp + 4) = make_float4(acc[4], acc[5], acc[6], acc[7]);
}

// scan pass 2: exclusive prefix of S over chunks (in place)
__global__ void state_p2()
{
    int bh = blockIdx.x, tid = threadIdx.x;   // 256 threads, float4 each
    float4 run = make_float4(0, 0, 0, 0);
    for (int c = 0; c < NCH; c++) {
        float4* p = (float4*)&g_S[(size_t)(bh * NCH + c) * (LH * DH) + tid * 4];
        float4 v = *p;
        *p = run;
        run.x += v.x; run.y += v.y; run.z += v.z; run.w += v.w;
    }
}

// ============================================================
// scan pass 3: in-chunk sequential scan, carry in registers.
// 64 threads, thread d owns carry[0..15][d].
// y[b][t][h*64+d] = sum_l w[t,l]*carry[l,d],  carry += ke[t,l]*v[t,d]
// ============================================================
__global__ __launch_bounds__(64) void scan_p3()
{
    int chunk = blockIdx.x, h = blockIdx.y, b = blockIdx.z;
    int tid = threadIdx.x;   // d
    __shared__ float ke_s[16][16];
    __shared__ float w_s[16][16];
    __shared__ float v_s[16][64];
    float carry[16];
    const float* Sp = &g_S[(size_t)((b * H_ + h) * NCH + chunk) * (LH * DH)];
#pragma unroll
    for (int l = 0; l < 16; l++) carry[l] = Sp[l * 64 + tid];
    int t0 = chunk * CSZ;

    for (int tt = 0; tt < CSZ; tt += 16) {
#pragma unroll
        for (int r = 0; r < 4; r++) {
            int f = r * 64 + tid, tr = f >> 4, li = f & 15;
            int src = (b * T_ + t0 + tt + tr) * L_ + h * LH + li;
            ke_s[tr][li] = g_K[src];
            w_s[tr][li]  = g_Q[src];
        }
#pragma unroll
        for (int r = 0; r < 4; r++) {
            int f = r * 64 + tid, tr = f >> 4, dq = f & 15;
            *(float4*)&v_s[tr][dq * 4] =
                *(const float4*)&g_V[(b * T_ + t0 + tt + tr) * D_ + h * DH + dq * 4];
        }
        __syncthreads();
#pragma unroll
        for (int k = 0; k < 16; k++) {
            float v = v_s[k][tid];
            float4 ke0 = *(const float4*)&ke_s[k][0];
            float4 ke1 = *(const float4*)&ke_s[k][4];
            float4 ke2 = *(const float4*)&ke_s[k][8];
            float4 ke3 = *(const float4*)&ke_s[k][12];
            float4 w0 = *(const float4*)&w_s[k][0];
            float4 w1 = *(const float4*)&w_s[k][4];
            float4 w2 = *(const float4*)&w_s[k][8];
            float4 w3 = *(const float4*)&w_s[k][12];
            float y = 0.f;
            carry[0]  = fmaf(ke0.x, v, carry[0]);  y = fmaf(w0.x, carry[0],  y);
            carry[1]  = fmaf(ke0.y, v, carry[1]);  y = fmaf(w0.y, carry[1],  y);
            carry[2]  = fmaf(ke0.z, v, carry[2]);  y = fmaf(w0.z, carry[2],  y);
            carry[3]  = fmaf(ke0.w, v, carry[3]);  y = fmaf(w0.w, carry[3],  y);
            carry[4]  = fmaf(ke1.x, v, carry[4]);  y = fmaf(w1.x, carry[4],  y);
            carry[5]  = fmaf(ke1.y, v, carry[5]);  y = fmaf(w1.y, carry[5],  y);
            carry[6]  = fmaf(ke1.z, v, carry[6]);  y = fmaf(w1.z, carry[6],  y);
            carry[7]  = fmaf(ke1.w, v, carry[7]);  y = fmaf(w1.w, carry[7],  y);
            carry[8]  = fmaf(ke2.x, v, carry[8]);  y = fmaf(w2.x, carry[8],  y);
            carry[9]  = fmaf(ke2.y, v, carry[9]);  y = fmaf(w2.y, carry[9],  y);
            carry[10] = fmaf(ke2.z, v, carry[10]); y = fmaf(w2.z, carry[10], y);
            carry[11] = fmaf(ke2.w, v, carry[11]); y = fmaf(w2.w, carry[11], y);
            carry[12] = fmaf(ke3.x, v, carry[12]); y = fmaf(w3.x, carry[12], y);
            carry[13] = fmaf(ke3.y, v, carry[13]); y = fmaf(w3.y, carry[13], y);
            carry[14] = fmaf(ke3.z, v, carry[14]); y = fmaf(w3.z, carry[14], y);
            carry[15] = fmaf(ke3.w, v, carry[15]); y = fmaf(w3.w, carry[15], y);
            g_y[(b * T_ + t0 + tt + k) * D_ + h * DH + tid] = y;
        }
        __syncthreads();
    }
}

// ============================================================
// permutation:  g_yp[(dh/8)][(dh%8)*512 + t/8][(t%8)*64 + b*8 + h] = y[b][t][h*64+dh]
// Tile = y[b][t0..t0+8][0..512): coalesced reads, 32B-aligned 8-float writes.
// ============================================================
__global__ __launch_bounds__(256) void transpose_k()
{
    int t8 = blockIdx.x, b = blockIdx.y;
    int tid = threadIdx.x;
    __shared__ float ys[8][512];
#pragma unroll
    for (int r = 0; r < 4; r++) {
        int f = r * 256 + tid, tr = f >> 7, c4 = f & 127;
        *(float4*)&ys[tr][c4 * 4] =
            *(const float4*)&g_y[(size_t)(b * T_ + t8 * 8 + tr) * D_ + c4 * 4];
    }
    __syncthreads();
#pragma unroll
    for (int r = 0; r < 2; r++) {
        int p = r * 256 + tid;
        int k = p >> 6, dh = p & 63;
        float v[8];
#pragma unroll
        for (int hh = 0; hh < 8; hh++) v[hh] = ys[k][hh * 64 + dh];
        int bp = dh >> 3, e = dh & 7;
        float* dst = &g_yp[(size_t)bp * (T_ * D_) + (size_t)(e * 512 + t8) * D_ + k * 64 + b * 8];
        *(float4*)dst       = make_float4(v[0], v[1], v[2], v[3]);
        *(float4*)(dst + 4) = make_float4(v[4], v[5], v[6], v[7]);
    }
}

// ============================================================
extern "C" void kernel_launch(void* const* d_in, const int* in_sizes, int n_in,
                              void* d_out, int out_size)
{
    const float* X  = (const float*)d_in[0];
    const float* Wk = (const float*)d_in[1];
    const float* Wq = (const float*)d_in[2];
    const float* Wv = (const float*)d_in[3];
    const float* Wo = (const float*)d_in[4];
    float* out = (float*)d_out;

    float *pQ, *pK, *pV, *pYP;
    cudaGetSymbolAddress((void**)&pQ,  g_Q);
    cudaGetSymbolAddress((void**)&pK,  g_K);
    cudaGetSymbolAddress((void**)&pV,  g_V);
    cudaGetSymbolAddress((void**)&pYP, g_yp);

    // projections
    sgemm<0><<<dim3(1, 256), 256>>>(X, Wq, pQ, M_, L_, D_);
    sgemm<1><<<dim3(1, 256), 256>>>(X, Wk, pK, M_, L_, D_);   // K_exp = exp(K/8)
    sgemm<0><<<dim3(4, 256), 256>>>(X, Wv, pV, M_, D_, D_);

    // qs_pre = softmax(Q/8) over Lh (in place in g_Q)
    softmax_kernel<<<M_, 128>>>();

    // alpha cumsum + w = qs_pre/alpha (in place in g_Q)
    alpha_p1<<<dim3(NCH, B_), 128>>>();
    alpha_p2<<<B_, 128>>>();
    alpha_p3<<<dim3(NCH, B_), 128>>>();

    // chunk-parallel state scan
    state_p1<<<dim3(NCH, H_, B_), 128>>>();
    state_p2<<<B_ * H_, 256>>>();
    scan_p3<<<dim3(NCH, H_, B_), 64>>>();

    // permutation + output projection
    transpose_k<<<dim3(T_ / 8, B_), 256>>>();
    sgemm<0><<<dim3(4, 256), 256>>>(pYP, Wo, out, M_, D_, D_);
}

// round 5
// speedup vs baseline: 1.7801x; 1.7801x over previous
#include <cuda_runtime.h>
#include <cuda_bf16.h>
#include <cstdint>

#define T_  4096
#define B_  8
#define D_  512
#define L_  128
#define H_  8
#define DH  64
#define LH  16
#define M_  (B_*T_)     // 32768 rows
#define NCH 32          // chunks over T
#define CSZ 128         // chunk size (T_/NCH)

// ---------------- scratch ----------------
__device__ float g_Q[M_*L_];
__device__ float g_K[M_*L_];
__device__ float g_V[M_*D_];
__device__ float g_y[M_*D_];
__device__ float g_csum[B_*NCH*L_];
__device__ float g_S[B_*H_*NCH*LH*DH];
// bf16 split operands (ushort bit patterns), all K-contiguous rows of 512
__device__ unsigned short g_Xh[M_*D_];
__device__ unsigned short g_Xl[M_*D_];
__device__ unsigned short g_Yh[M_*D_];
__device__ unsigned short g_Yl[M_*D_];
__device__ unsigned short g_Wqh[L_*D_], g_Wql[L_*D_];   // W^T layouts [N][K=512]
__device__ unsigned short g_Wkh[L_*D_], g_Wkl[L_*D_];
__device__ unsigned short g_Wvh[D_*D_], g_Wvl[D_*D_];
__device__ unsigned short g_Woh[D_*D_], g_Wol[D_*D_];

// ---------------- portable PTX helpers (sm_80+; no 'a'-only features) ----------
__device__ __forceinline__ uint32_t smem_u32(const void* p) {
    uint32_t a;
    asm("{ .reg .u64 t; cvta.to.shared.u64 t, %1; cvt.u32.u64 %0, t; }" : "=r"(a) : "l"(p));
    return a;
}
__device__ __forceinline__ void ldsm4(uint32_t* r, uint32_t addr) {
    asm volatile("ldmatrix.sync.aligned.m8n8.x4.shared.b16 {%0,%1,%2,%3}, [%4];"
                 : "=r"(r[0]), "=r"(r[1]), "=r"(r[2]), "=r"(r[3]) : "r"(addr));
}
__device__ __forceinline__ void mma16816(float* d, const uint32_t* a, const uint32_t* b) {
    asm volatile("mma.sync.aligned.m16n8k16.row.col.f32.bf16.bf16.f32 "
                 "{%0,%1,%2,%3}, {%4,%5,%6,%7}, {%8,%9}, {%0,%1,%2,%3};"
                 : "+f"(d[0]), "+f"(d[1]), "+f"(d[2]), "+f"(d[3])
                 : "r"(a[0]), "r"(a[1]), "r"(a[2]), "r"(a[3]), "r"(b[0]), "r"(b[1]));
}
#define CP_ASYNC16(dst, src) \
    asm volatile("cp.async.cg.shared.global [%0], [%1], 16;" :: "r"(dst), "l"(src))
#define CP_COMMIT() asm volatile("cp.async.commit_group;" ::: "memory")
#define CP_WAIT(n)  asm volatile("cp.async.wait_group %0;" :: "n"(n) : "memory")

// ============================================================
// bf16x3 GEMM via mma.sync: C[M,N] = A[M,512] @ Bt[N,512]^T (fp32)
// Tile 128x128, BK=32, 256 thr (8 warps, 2m x 4n), warp tile 64x32.
// SMEM rows padded: 32 bf16 (64B) + 16B pad = 80B stride.
// EPI==1: C = exp(0.125*acc)
// ============================================================
#define ROWB 80
#define MATB (128 * ROWB)          // 10240 bytes per matrix
#define BUFB (4 * MATB)            // Ah,Al,Bh,Bl
#define GEMM_SMEM (2 * BUFB)       // double buffer = 81920

__device__ __forceinline__ void issue_loads(const unsigned short* ah, const unsigned short* al,
                                            const unsigned short* bh, const unsigned short* bl,
                                            int k0, uint32_t smbuf, int tid)
{
#pragma unroll
    for (int half = 0; half < 2; half++) {
        int c = half * 256 + tid;
        int r = c >> 2, s = c & 3;
        uint32_t soff = (uint32_t)(r * ROWB + s * 16);
        const unsigned short* g = ah + (size_t)r * 512 + k0 + s * 8;
        CP_ASYNC16(smbuf + 0 * MATB + soff, g);
        g = al + (size_t)r * 512 + k0 + s * 8;
        CP_ASYNC16(smbuf + 1 * MATB + soff, g);
        g = bh + (size_t)r * 512 + k0 + s * 8;
        CP_ASYNC16(smbuf + 2 * MATB + soff, g);
        g = bl + (size_t)r * 512 + k0 + s * 8;
        CP_ASYNC16(smbuf + 3 * MATB + soff, g);
    }
}

template<int EPI>
__global__ __launch_bounds__(256) void gemm_mma(const unsigned short* __restrict__ Ah,
                                                const unsigned short* __restrict__ Al,
                                                const unsigned short* __restrict__ Bh,
                                                const unsigned short* __restrict__ Bl,
                                                float* __restrict__ C, int N)
{
    extern __shared__ char sm[];
    const int tid = threadIdx.x;
    const int wid = tid >> 5, lane = tid & 31;
    const int wm = wid >> 2, wn = wid & 3;     // 2 x 4 warp grid
    const int m0 = blockIdx.y * 128;
    const int n0 = blockIdx.x * 128;
    const uint32_t smb = smem_u32(sm);

    const unsigned short* ah = Ah + (size_t)m0 * 512;
    const unsigned short* al = Al + (size_t)m0 * 512;
    const unsigned short* bh = Bh + (size_t)n0 * 512;
    const unsigned short* bl = Bl + (size_t)n0 * 512;

    float acc[4][4][4];
#pragma unroll
    for (int i = 0; i < 4; i++)
#pragma unroll
        for (int j = 0; j < 4; j++)
#pragma unroll
            for (int e = 0; e < 4; e++) acc[i][j][e] = 0.f;

    // per-lane ldmatrix address pieces
    const uint32_t a_lane = (uint32_t)((wm * 64 + (lane & 15)) * ROWB + (lane >> 4) * 16);
    const uint32_t b_lane = (uint32_t)((wn * 32 + (lane & 15)) * ROWB + (lane >> 4) * 16);

    // prefetch iter 0
    issue_loads(ah, al, bh, bl, 0, smb, tid);
    CP_COMMIT();

    const int NIT = 512 / 32;   // 16
    for (int ki = 0; ki < NIT; ki++) {
        const uint32_t buf = smb + (uint32_t)(ki & 1) * BUFB;
        if (ki + 1 < NIT) {
            issue_loads(ah, al, bh, bl, (ki + 1) * 32, smb + (uint32_t)((ki + 1) & 1) * BUFB, tid);
            CP_COMMIT();
            CP_WAIT(1);
        } else {
            CP_WAIT(0);
        }
        __syncthreads();

#pragma unroll
        for (int ks = 0; ks < 2; ks++) {
            const uint32_t koff = (uint32_t)(ks * 32);
            uint32_t fAh[4][4], fAl[4][4];
#pragma unroll
            for (int mf = 0; mf < 4; mf++) {
                ldsm4(fAh[mf], buf + 0 * MATB + a_lane + (uint32_t)(mf * 16 * ROWB) + koff);
                ldsm4(fAl[mf], buf + 1 * MATB + a_lane + (uint32_t)(mf * 16 * ROWB) + koff);
            }
            uint32_t fBh[4][2], fBl[4][2];
#pragma unroll
            for (int p = 0; p < 2; p++) {
                uint32_t r[4];
                ldsm4(r, buf + 2 * MATB + b_lane + (uint32_t)(p * 16 * ROWB) + koff);
                fBh[2 * p][0] = r[0]; fBh[2 * p][1] = r[2];
                fBh[2 * p + 1][0] = r[1]; fBh[2 * p + 1][1] = r[3];
                ldsm4(r, buf + 3 * MATB + b_lane + (uint32_t)(p * 16 * ROWB) + koff);
                fBl[2 * p][0] = r[0]; fBl[2 * p][1] = r[2];
                fBl[2 * p + 1][0] = r[1]; fBl[2 * p + 1][1] = r[3];
            }
#pragma unroll
            for (int mf = 0; mf < 4; mf++)
#pragma unroll
                for (int nf = 0; nf < 4; nf++) {
                    mma16816(acc[mf][nf], fAh[mf], fBh[nf]);
                    mma16816(acc[mf][nf], fAh[mf], fBl[nf]);
                    mma16816(acc[mf][nf], fAl[mf], fBh[nf]);
                }
        }
        __syncthreads();
    }

    // epilogue
    const int rr = lane >> 2, cc = (lane & 3) * 2;
#pragma unroll
    for (int mf = 0; mf < 4; mf++) {
#pragma unroll
        for (int nf = 0; nf < 4; nf++) {
            int row = m0 + wm * 64 + mf * 16 + rr;
            int col = n0 + wn * 32 + nf * 8 + cc;
            float d0 = acc[mf][nf][0], d1 = acc[mf][nf][1];
            float d2 = acc[mf][nf][2], d3 = acc[mf][nf][3];
            if (EPI) {
                d0 = __expf(0.125f * d0); d1 = __expf(0.125f * d1);
                d2 = __expf(0.125f * d2); d3 = __expf(0.125f * d3);
            }
            *(float2*)(C + (size_t)row * N + col)       = make_float2(d0, d1);
            *(float2*)(C + (size_t)(row + 8) * N + col) = make_float2(d2, d3);
        }
    }
}

// ============================================================
// split-precision conversions
// ============================================================
__device__ __forceinline__ void split2(float x, unsigned short& h, unsigned short& l) {
    __nv_bfloat16 hb = __float2bfloat16(x);
    __nv_bfloat16 lb = __float2bfloat16(x - __bfloat162float(hb));
    h = __bfloat16_as_ushort(hb);
    l = __bfloat16_as_ushort(lb);
}
__global__ void conv_X(const float* __restrict__ X)
{
    int i = blockIdx.x * 256 + threadIdx.x;
    float4 v = ((const float4*)X)[i];
    ushort4 h, l;
    split2(v.x, h.x, l.x); split2(v.y, h.y, l.y);
    split2(v.z, h.z, l.z); split2(v.w, h.w, l.w);
    ((ushort4*)g_Xh)[i] = h;
    ((ushort4*)g_Xl)[i] = l;
}
__global__ void conv_Wt(const float* __restrict__ W, unsigned short* __restrict__ Th,
                        unsigned short* __restrict__ Tl, int N)
{
    int id = blockIdx.x * 256 + threadIdx.x;
    int n = id % N, k = id / N;
    unsigned short h, l;
    split2(W[id], h, l);
    Th[n * 512 + k] = h;
    Tl[n * 512 + k] = l;
}

// ============================================================
// softmax over Lh=16 per (b,t,h)
// ============================================================
__global__ void softmax_kernel()
{
    int bt = blockIdx.x;
    int l = threadIdx.x;
    int idx = bt * L_ + l;
    float q = g_Q[idx] * 0.125f;
    float m = q;
#pragma unroll
    for (int s = 8; s >= 1; s >>= 1)
        m = fmaxf(m, __shfl_xor_sync(0xffffffffu, m, s));
    float e = __expf(q - m);
    float sum = e;
#pragma unroll
    for (int s = 8; s >= 1; s >>= 1)
        sum += __shfl_xor_sync(0xffffffffu, sum, s);
    g_Q[idx] = e / sum;
}

// ============================================================
// alpha cumsum + w = qs/alpha
// ============================================================
__global__ void alpha_p1()
{
    int chunk = blockIdx.x, b = blockIdx.y, l = threadIdx.x;
    float s = 0.f;
    int base = (b * T_ + chunk * CSZ) * L_ + l;
    for (int i = 0; i < CSZ; i++) s += g_K[base + i * L_];
    g_csum[(b * NCH + chunk) * L_ + l] = s;
}
__global__ void alpha_p2()
{
    int b = blockIdx.x, l = threadIdx.x;
    float run = 0.f;
    for (int c = 0; c < NCH; c++) {
        int idx = (b * NCH + c) * L_ + l;
        float v = g_csum[idx];
        g_csum[idx] = run;
        run += v;
    }
}
__global__ void alpha_p3()
{
    int chunk = blockIdx.x, b = blockIdx.y, l = threadIdx.x;
    float a = g_csum[(b * NCH + chunk) * L_ + l];
    int base = (b * T_ + chunk * CSZ) * L_ + l;
    for (int i = 0; i < CSZ; i++) {
        int idx = base + i * L_;
        a += g_K[idx];
        g_Q[idx] = __fdividef(g_Q[idx], a);
    }
}

// ============================================================
// scan passes
// ============================================================
__global__ __launch_bounds__(128) void state_p1()
{
    int chunk = blockIdx.x, h = blockIdx.y, b = blockIdx.z;
    int tid = threadIdx.x;
    int l = tid >> 3, d0 = (tid & 7) * 8;
    __shared__ float ke_s[16][16];
    __shared__ float v_s[16][64];
    float acc[8] = {0, 0, 0, 0, 0, 0, 0, 0};
    int t0 = chunk * CSZ;
    for (int tt = 0; tt < CSZ; tt += 16) {
#pragma unroll
        for (int r = 0; r < 2; r++) {
            int f = r * 128 + tid, tr = f >> 4, li = f & 15;
            ke_s[tr][li] = g_K[(b * T_ + t0 + tt + tr) * L_ + h * LH + li];
        }
#pragma unroll
        for (int r = 0; r < 2; r++) {
            int f = r * 128 + tid, tr = f >> 4, dq = f & 15;
            *(float4*)&v_s[tr][dq * 4] =
                *(const float4*)&g_V[(b * T_ + t0 + tt + tr) * D_ + h * DH + dq * 4];
        }
        __syncthreads();
#pragma unroll
        for (int k = 0; k < 16; k++) {
            float kl = ke_s[k][l];
            float4 va = *(const float4*)&v_s[k][d0];
            float4 vb = *(const float4*)&v_s[k][d0 + 4];
            acc[0] = fmaf(kl, va.x, acc[0]); acc[1] = fmaf(kl, va.y, acc[1]);
            acc[2] = fmaf(kl, va.z, acc[2]); acc[3] = fmaf(kl, va.w, acc[3]);
            acc[4] = fmaf(kl, vb.x, acc[4]); acc[5] = fmaf(kl, vb.y, acc[5]);
            acc[6] = fmaf(kl, vb.z, acc[6]); acc[7] = fmaf(kl, vb.w, acc[7]);
        }
        __syncthreads();
    }
    float* Sp = &g_S[(((b * H_ + h) * NCH + chunk) * LH + l) * DH + d0];
    *(float4*)Sp       = make_float4(acc[0], acc[1], acc[2], acc[3]);
    *(float4*)(Sp + 4) = make_float4(acc[4], acc[5], acc[6], acc[7]);
}
__global__ void state_p2()
{
    int bh = blockIdx.x, tid = threadIdx.x;
    float4 run = make_float4(0, 0, 0, 0);
    for (int c = 0; c < NCH; c++) {
        float4* p = (float4*)&g_S[(size_t)(bh * NCH + c) * (LH * DH) + tid * 4];
        float4 v = *p;
        *p = run;
        run.x += v.x; run.y += v.y; run.z += v.z; run.w += v.w;
    }
}
__global__ __launch_bounds__(64) void scan_p3()
{
    int chunk = blockIdx.x, h = blockIdx.y, b = blockIdx.z;
    int tid = threadIdx.x;
    __shared__ float ke_s[16][16];
    __shared__ float w_s[16][16];
    __shared__ float v_s[16][64];
    float carry[16];
    const float* Sp = &g_S[(size_t)((b * H_ + h) * NCH + chunk) * (LH * DH)];
#pragma unroll
    for (int l = 0; l < 16; l++) carry[l] = Sp[l * 64 + tid];
    int t0 = chunk * CSZ;

    for (int tt = 0; tt < CSZ; tt += 16) {
#pragma unroll
        for (int r = 0; r < 4; r++) {
            int f = r * 64 + tid, tr = f >> 4, li = f & 15;
            int src = (b * T_ + t0 + tt + tr) * L_ + h * LH + li;
            ke_s[tr][li] = g_K[src];
            w_s[tr][li]  = g_Q[src];
        }
#pragma unroll
        for (int r = 0; r < 4; r++) {
            int f = r * 64 + tid, tr = f >> 4, dq = f & 15;
            *(float4*)&v_s[tr][dq * 4] =
                *(const float4*)&g_V[(b * T_ + t0 + tt + tr) * D_ + h * DH + dq * 4];
        }
        __syncthreads();
#pragma unroll
        for (int k = 0; k < 16; k++) {
            float v = v_s[k][tid];
            float4 ke0 = *(const float4*)&ke_s[k][0];
            float4 ke1 = *(const float4*)&ke_s[k][4];
            float4 ke2 = *(const float4*)&ke_s[k][8];
            float4 ke3 = *(const float4*)&ke_s[k][12];
            float4 w0 = *(const float4*)&w_s[k][0];
            float4 w1 = *(const float4*)&w_s[k][4];
            float4 w2 = *(const float4*)&w_s[k][8];
            float4 w3 = *(const float4*)&w_s[k][12];
            float y = 0.f;
            carry[0]  = fmaf(ke0.x, v, carry[0]);  y = fmaf(w0.x, carry[0],  y);
            carry[1]  = fmaf(ke0.y, v, carry[1]);  y = fmaf(w0.y, carry[1],  y);
            carry[2]  = fmaf(ke0.z, v, carry[2]);  y = fmaf(w0.z, carry[2],  y);
            carry[3]  = fmaf(ke0.w, v, carry[3]);  y = fmaf(w0.w, carry[3],  y);
            carry[4]  = fmaf(ke1.x, v, carry[4]);  y = fmaf(w1.x, carry[4],  y);
            carry[5]  = fmaf(ke1.y, v, carry[5]);  y = fmaf(w1.y, carry[5],  y);
            carry[6]  = fmaf(ke1.z, v, carry[6]);  y = fmaf(w1.z, carry[6],  y);
            carry[7]  = fmaf(ke1.w, v, carry[7]);  y = fmaf(w1.w, carry[7],  y);
            carry[8]  = fmaf(ke2.x, v, carry[8]);  y = fmaf(w2.x, carry[8],  y);
            carry[9]  = fmaf(ke2.y, v, carry[9]);  y = fmaf(w2.y, carry[9],  y);
            carry[10] = fmaf(ke2.z, v, carry[10]); y = fmaf(w2.z, carry[10], y);
            carry[11] = fmaf(ke2.w, v, carry[11]); y = fmaf(w2.w, carry[11], y);
            carry[12] = fmaf(ke3.x, v, carry[12]); y = fmaf(w3.x, carry[12], y);
            carry[13] = fmaf(ke3.y, v, carry[13]); y = fmaf(w3.y, carry[13], y);
            carry[14] = fmaf(ke3.z, v, carry[14]); y = fmaf(w3.z, carry[14], y);
            carry[15] = fmaf(ke3.w, v, carry[15]); y = fmaf(w3.w, carry[15], y);
            g_y[(b * T_ + t0 + tt + k) * D_ + h * DH + tid] = y;
        }
        __syncthreads();
    }
}

// ============================================================
// permutation (writes bf16 hi/lo directly for the O GEMM)
// ============================================================
__global__ __launch_bounds__(256) void transpose_k()
{
    int t8 = blockIdx.x, b = blockIdx.y;
    int tid = threadIdx.x;
    __shared__ float ys[8][512];
#pragma unroll
    for (int r = 0; r < 4; r++) {
        int f = r * 256 + tid, tr = f >> 7, c4 = f & 127;
        *(float4*)&ys[tr][c4 * 4] =
            *(const float4*)&g_y[(size_t)(b * T_ + t8 * 8 + tr) * D_ + c4 * 4];
    }
    __syncthreads();
#pragma unroll
    for (int r = 0; r < 2; r++) {
        int p = r * 256 + tid;
        int k = p >> 6, dh = p & 63;
        unsigned short hv[8], lv[8];
#pragma unroll
        for (int hh = 0; hh < 8; hh++) split2(ys[k][hh * 64 + dh], hv[hh], lv[hh]);
        int bp = dh >> 3, e = dh & 7;
        size_t didx = (size_t)bp * (T_ * D_) + (size_t)(e * 512 + t8) * D_ + k * 64 + b * 8;
        *(uint4*)(g_Yh + didx) = *(uint4*)hv;
        *(uint4*)(g_Yl + didx) = *(uint4*)lv;
    }
}

// ============================================================
extern "C" void kernel_launch(void* const* d_in, const int* in_sizes, int n_in,
                              void* d_out, int out_size)
{
    const float* X  = (const float*)d_in[0];
    const float* Wk = (const float*)d_in[1];
    const float* Wq = (const float*)d_in[2];
    const float* Wv = (const float*)d_in[3];
    const float* Wo = (const float*)d_in[4];
    float* out = (float*)d_out;

    float *pQ, *pK, *pV;
    unsigned short *pXh, *pXl, *pYh, *pYl;
    unsigned short *pWqh, *pWql, *pWkh, *pWkl, *pWvh, *pWvl, *pWoh, *pWol;
    cudaGetSymbolAddress((void**)&pQ, g_Q);
    cudaGetSymbolAddress((void**)&pK, g_K);
    cudaGetSymbolAddress((void**)&pV, g_V);
    cudaGetSymbolAddress((void**)&pXh, g_Xh);
    cudaGetSymbolAddress((void**)&pXl, g_Xl);
    cudaGetSymbolAddress((void**)&pYh, g_Yh);
    cudaGetSymbolAddress((void**)&pYl, g_Yl);
    cudaGetSymbolAddress((void**)&pWqh, g_Wqh);
    cudaGetSymbolAddress((void**)&pWql, g_Wql);
    cudaGetSymbolAddress((void**)&pWkh, g_Wkh);
    cudaGetSymbolAddress((void**)&pWkl, g_Wkl);
    cudaGetSymbolAddress((void**)&pWvh, g_Wvh);
    cudaGetSymbolAddress((void**)&pWvl, g_Wvl);
    cudaGetSymbolAddress((void**)&pWoh, g_Woh);
    cudaGetSymbolAddress((void**)&pWol, g_Wol);

    cudaFuncSetAttribute(gemm_mma<0>, cudaFuncAttributeMaxDynamicSharedMemorySize, GEMM_SMEM);
    cudaFuncSetAttribute(gemm_mma<1>, cudaFuncAttributeMaxDynamicSharedMemorySize, GEMM_SMEM);

    // split-precision conversions
    conv_X<<<M_ * D_ / 1024, 256>>>(X);
    conv_Wt<<<(D_ * L_) / 256, 256>>>(Wq, pWqh, pWql, L_);
    conv_Wt<<<(D_ * L_) / 256, 256>>>(Wk, pWkh, pWkl, L_);
    conv_Wt<<<(D_ * D_) / 256, 256>>>(Wv, pWvh, pWvl, D_);
    conv_Wt<<<(D_ * D_) / 256, 256>>>(Wo, pWoh, pWol, D_);

    // tensor-core projections (bf16x3 -> fp32 via mma.sync)
    gemm_mma<0><<<dim3(1, 256), 256, GEMM_SMEM>>>(pXh, pXl, pWqh, pWql, pQ, L_);
    gemm_mma<1><<<dim3(1, 256), 256, GEMM_SMEM>>>(pXh, pXl, pWkh, pWkl, pK, L_);  // exp epi
    gemm_mma<0><<<dim3(4, 256), 256, GEMM_SMEM>>>(pXh, pXl, pWvh, pWvl, pV, D_);

    // softmax + alpha + w
    softmax_kernel<<<M_, 128>>>();
    alpha_p1<<<dim3(NCH, B_), 128>>>();
    alpha_p2<<<B_, 128>>>();
    alpha_p3<<<dim3(NCH, B_), 128>>>();

    // chunk-parallel state scan
    state_p1<<<dim3(NCH, H_, B_), 128>>>();
    state_p2<<<B_ * H_, 256>>>();
    scan_p3<<<dim3(NCH, H_, B_), 64>>>();

    // permutation (+ bf16 split) and output projection
    transpose_k<<<dim3(T_ / 8, B_), 256>>>();
    gemm_mma<0><<<dim3(4, 256), 256, GEMM_SMEM>>>(pYh, pYl, pWoh, pWol, out, D_);
}

// round 6
// speedup vs baseline: 1.8422x; 1.0349x over previous
#include <cuda_runtime.h>
#include <cuda_bf16.h>
#include <cstdint>

#define T_  4096
#define B_  8
#define D_  512
#define L_  128
#define H_  8
#define DH  64
#define LH  16
#define M_  (B_*T_)
#define NCH 32
#define CSZ 128

// ---------------- scratch ----------------
__device__ float g_Q[M_*L_];
__device__ float g_K[M_*L_];
__device__ float g_V[M_*D_];
__device__ float g_y[M_*D_];
__device__ float g_csum[B_*NCH*L_];
__device__ float g_S[B_*H_*NCH*LH*DH];
__device__ unsigned short g_Xh[M_*D_];
__device__ unsigned short g_Xl[M_*D_];
__device__ unsigned short g_Yh[M_*D_];
__device__ unsigned short g_Yl[M_*D_];
__device__ unsigned short g_Wqkh[2*L_*D_], g_Wqkl[2*L_*D_]; // [256][512] Wq|Wk ^T
__device__ unsigned short g_Wvh[D_*D_], g_Wvl[D_*D_];
__device__ unsigned short g_Woh[D_*D_], g_Wol[D_*D_];

// ---------------- portable PTX helpers ----------------
__device__ __forceinline__ uint32_t smem_u32(const void* p) {
    uint32_t a;
    asm("{ .reg .u64 t; cvta.to.shared.u64 t, %1; cvt.u32.u64 %0, t; }" : "=r"(a) : "l"(p));
    return a;
}
__device__ __forceinline__ void ldsm4(uint32_t* r, uint32_t addr) {
    asm volatile("ldmatrix.sync.aligned.m8n8.x4.shared.b16 {%0,%1,%2,%3}, [%4];"
                 : "=r"(r[0]), "=r"(r[1]), "=r"(r[2]), "=r"(r[3]) : "r"(addr));
}
__device__ __forceinline__ void mma16816(float* d, const uint32_t* a, const uint32_t* b) {
    asm volatile("mma.sync.aligned.m16n8k16.row.col.f32.bf16.bf16.f32 "
                 "{%0,%1,%2,%3}, {%4,%5,%6,%7}, {%8,%9}, {%0,%1,%2,%3};"
                 : "+f"(d[0]), "+f"(d[1]), "+f"(d[2]), "+f"(d[3])
                 : "r"(a[0]), "r"(a[1]), "r"(a[2]), "r"(a[3]), "r"(b[0]), "r"(b[1]));
}
#define CP_ASYNC16(dst, src) \
    asm volatile("cp.async.cg.shared.global [%0], [%1], 16;" :: "r"(dst), "l"(src))
#define CP_COMMIT() asm volatile("cp.async.commit_group;" ::: "memory")
#define CP_WAIT(n)  asm volatile("cp.async.wait_group %0;" :: "n"(n) : "memory")

// ============================================================
// bf16 split GEMM via mma.sync. Tile 128x128, BK=32, 256 thr.
// MODE 0: 3-term, C[M,512] plain.           (V proj / O proj)
// MODE 1: 2-term (Ah*Bh + Ah*Bl), fused QK: blockIdx.x==0 -> g_Q,
//         blockIdx.x==1 -> g_K with exp(0.125*) epilogue.
// ============================================================
#define ROWB 80
#define MATB (128 * ROWB)
#define BUFB (4 * MATB)
#define GEMM_SMEM (2 * BUFB)

template<int LOADAL>
__device__ __forceinline__ void issue_loads(const unsigned short* ah, const unsigned short* al,
                                            const unsigned short* bh, const unsigned short* bl,
                                            int k0, uint32_t smbuf, int tid)
{
#pragma unroll
    for (int half = 0; half < 2; half++) {
        int c = half * 256 + tid;
        int r = c >> 2, s = c & 3;
        uint32_t soff = (uint32_t)(r * ROWB + s * 16);
        CP_ASYNC16(smbuf + 0 * MATB + soff, ah + (size_t)r * 512 + k0 + s * 8);
        if (LOADAL)
            CP_ASYNC16(smbuf + 1 * MATB + soff, al + (size_t)r * 512 + k0 + s * 8);
        CP_ASYNC16(smbuf + 2 * MATB + soff, bh + (size_t)r * 512 + k0 + s * 8);
        CP_ASYNC16(smbuf + 3 * MATB + soff, bl + (size_t)r * 512 + k0 + s * 8);
    }
}

template<int MODE>
__global__ __launch_bounds__(256, 2) void gemm_mma(const unsigned short* __restrict__ Ah,
                                                   const unsigned short* __restrict__ Al,
                                                   const unsigned short* __restrict__ Bh,
                                                   const unsigned short* __restrict__ Bl,
                                                   float* __restrict__ C, int N)
{
    extern __shared__ char sm[];
    const int tid = threadIdx.x;
    const int wid = tid >> 5, lane = tid & 31;
    const int wm = wid >> 2, wn = wid & 3;
    const int m0 = blockIdx.y * 128;
    const int n0 = blockIdx.x * 128;
    const uint32_t smb = smem_u32(sm);

    const unsigned short* ah = Ah + (size_t)m0 * 512;
    const unsigned short* al = Al + (size_t)m0 * 512;
    const unsigned short* bh = Bh + (size_t)n0 * 512;
    const unsigned short* bl = Bl + (size_t)n0 * 512;

    float acc[4][4][4];
#pragma unroll
    for (int i = 0; i < 4; i++)
#pragma unroll
        for (int j = 0; j < 4; j++)
#pragma unroll
            for (int e = 0; e < 4; e++) acc[i][j][e] = 0.f;

    const uint32_t a_lane = (uint32_t)((wm * 64 + (lane & 15)) * ROWB + (lane >> 4) * 16);
    const uint32_t b_lane = (uint32_t)((wn * 32 + (lane & 15)) * ROWB + (lane >> 4) * 16);
    const int NTERMS = (MODE == 1) ? 2 : 3;

    issue_loads<(MODE != 1)>(ah, al, bh, bl, 0, smb, tid);
    CP_COMMIT();

    const int NIT = 512 / 32;
    for (int ki = 0; ki < NIT; ki++) {
        const uint32_t buf = smb + (uint32_t)(ki & 1) * BUFB;
        if (ki + 1 < NIT) {
            issue_loads<(MODE != 1)>(ah, al, bh, bl, (ki + 1) * 32,
                                     smb + (uint32_t)((ki + 1) & 1) * BUFB, tid);
            CP_COMMIT();
            CP_WAIT(1);
        } else {
            CP_WAIT(0);
        }
        __syncthreads();

#pragma unroll
        for (int ks = 0; ks < 2; ks++) {
            const uint32_t koff = (uint32_t)(ks * 32);
            // B fragments first (live across mf loop)
            uint32_t fBh[4][2], fBl[4][2];
#pragma unroll
            for (int p = 0; p < 2; p++) {
                uint32_t r[4];
                ldsm4(r, buf + 2 * MATB + b_lane + (uint32_t)(p * 16 * ROWB) + koff);
                fBh[2 * p][0] = r[0]; fBh[2 * p][1] = r[2];
                fBh[2 * p + 1][0] = r[1]; fBh[2 * p + 1][1] = r[3];
                ldsm4(r, buf + 3 * MATB + b_lane + (uint32_t)(p * 16 * ROWB) + koff);
                fBl[2 * p][0] = r[0]; fBl[2 * p][1] = r[2];
                fBl[2 * p + 1][0] = r[1]; fBl[2 * p + 1][1] = r[3];
            }
#pragma unroll
            for (int mf = 0; mf < 4; mf++) {
                uint32_t fAh[4];
                ldsm4(fAh, buf + 0 * MATB + a_lane + (uint32_t)(mf * 16 * ROWB) + koff);
#pragma unroll
                for (int nf = 0; nf < 4; nf++) {
                    mma16816(acc[mf][nf], fAh, fBh[nf]);
                    mma16816(acc[mf][nf], fAh, fBl[nf]);
                }
                if (NTERMS == 3) {
                    uint32_t fAl[4];
                    ldsm4(fAl, buf + 1 * MATB + a_lane + (uint32_t)(mf * 16 * ROWB) + koff);
#pragma unroll
                    for (int nf = 0; nf < 4; nf++)
                        mma16816(acc[mf][nf], fAl, fBh[nf]);
                }
            }
        }
        __syncthreads();
    }

    // epilogue
    const int rr = lane >> 2, cc = (lane & 3) * 2;
    float* Cout = C;
    int cstride = N;
    bool do_exp = false;
    if (MODE == 1) {
        Cout = (blockIdx.x == 0) ? g_Q : g_K;   // whole CTA uniform
        cstride = L_;
        do_exp = (blockIdx.x == 1);
    }
#pragma unroll
    for (int mf = 0; mf < 4; mf++) {
#pragma unroll
        for (int nf = 0; nf < 4; nf++) {
            int row = m0 + wm * 64 + mf * 16 + rr;
            int col = wn * 32 + nf * 8 + cc;
            if (MODE == 0) col += n0;
            float d0 = acc[mf][nf][0], d1 = acc[mf][nf][1];
            float d2 = acc[mf][nf][2], d3 = acc[mf][nf][3];
            if (MODE == 1 && do_exp) {
                d0 = __expf(0.125f * d0); d1 = __expf(0.125f * d1);
                d2 = __expf(0.125f * d2); d3 = __expf(0.125f * d3);
            }
            *(float2*)(Cout + (size_t)row * cstride + col)       = make_float2(d0, d1);
            *(float2*)(Cout + (size_t)(row + 8) * cstride + col) = make_float2(d2, d3);
        }
    }
}

// ============================================================
// conversions
// ============================================================
__device__ __forceinline__ void split2(float x, unsigned short& h, unsigned short& l) {
    __nv_bfloat16 hb = __float2bfloat16(x);
    __nv_bfloat16 lb = __float2bfloat16(x - __bfloat162float(hb));
    h = __bfloat16_as_ushort(hb);
    l = __bfloat16_as_ushort(lb);
}
__global__ void conv_X(const float* __restrict__ X)
{
    int i = blockIdx.x * 256 + threadIdx.x;
    float4 v = ((const float4*)X)[i];
    ushort4 h, l;
    split2(v.x, h.x, l.x); split2(v.y, h.y, l.y);
    split2(v.z, h.z, l.z); split2(v.w, h.w, l.w);
    ((ushort4*)g_Xh)[i] = h;
    ((ushort4*)g_Xl)[i] = l;
}
// W[512][N] -> dst rows [N][512] at row offset roff
__global__ void conv_Wt(const float* __restrict__ W, unsigned short* __restrict__ Th,
                        unsigned short* __restrict__ Tl, int N, int roff)
{
    int id = blockIdx.x * 256 + threadIdx.x;
    int n = id % N, k = id / N;
    unsigned short h, l;
    split2(W[id], h, l);
    Th[(roff + n) * 512 + k] = h;
    Tl[(roff + n) * 512 + k] = l;
}

// ============================================================
// alpha cumsum; p3 fuses softmax(Q/8) and w = softmax/alpha
// ============================================================
__global__ void alpha_p1()
{
    int chunk = blockIdx.x, b = blockIdx.y, l = threadIdx.x;
    float s = 0.f;
    int base = (b * T_ + chunk * CSZ) * L_ + l;
    for (int i = 0; i < CSZ; i++) s += g_K[base + i * L_];
    g_csum[(b * NCH + chunk) * L_ + l] = s;
}
__global__ void alpha_p2()
{
    int b = blockIdx.x, l = threadIdx.x;
    float run = 0.f;
    for (int c = 0; c < NCH; c++) {
        int idx = (b * NCH + c) * L_ + l;
        float v = g_csum[idx];
        g_csum[idx] = run;
        run += v;
    }
}
__global__ void alpha_p3()
{
    int chunk = blockIdx.x, b = blockIdx.y, l = threadIdx.x;
    float a = g_csum[(b * NCH + chunk) * L_ + l];
    int base = (b * T_ + chunk * CSZ) * L_ + l;
    for (int i = 0; i < CSZ; i++) {
        int idx = base + i * L_;
        a += g_K[idx];
        float q = g_Q[idx] * 0.125f;
        float m = q;
#pragma unroll
        for (int s = 8; s >= 1; s >>= 1)
            m = fmaxf(m, __shfl_xor_sync(0xffffffffu, m, s));
        float e = __expf(q - m);
        float sum = e;
#pragma unroll
        for (int s = 8; s >= 1; s >>= 1)
            sum += __shfl_xor_sync(0xffffffffu, sum, s);
        g_Q[idx] = __fdividef(e, sum * a);
    }
}

// ============================================================
// scan passes
// ============================================================
__global__ __launch_bounds__(128) void state_p1()
{
    int chunk = blockIdx.x, h = blockIdx.y, b = blockIdx.z;
    int tid = threadIdx.x;
    int l = tid >> 3, d0 = (tid & 7) * 8;
    __shared__ float ke_s[16][16];
    __shared__ float v_s[16][64];
    float acc[8] = {0, 0, 0, 0, 0, 0, 0, 0};
    int t0 = chunk * CSZ;
    for (int tt = 0; tt < CSZ; tt += 16) {
#pragma unroll
        for (int r = 0; r < 2; r++) {
            int f = r * 128 + tid, tr = f >> 4, li = f & 15;
            ke_s[tr][li] = g_K[(b * T_ + t0 + tt + tr) * L_ + h * LH + li];
        }
#pragma unroll
        for (int r = 0; r < 2; r++) {
            int f = r * 128 + tid, tr = f >> 4, dq = f & 15;
            *(float4*)&v_s[tr][dq * 4] =
                *(const float4*)&g_V[(b * T_ + t0 + tt + tr) * D_ + h * DH + dq * 4];
        }
        __syncthreads();
#pragma unroll
        for (int k = 0; k < 16; k++) {
            float kl = ke_s[k][l];
            float4 va = *(const float4*)&v_s[k][d0];
            float4 vb = *(const float4*)&v_s[k][d0 + 4];
            acc[0] = fmaf(kl, va.x, acc[0]); acc[1] = fmaf(kl, va.y, acc[1]);
            acc[2] = fmaf(kl, va.z, acc[2]); acc[3] = fmaf(kl, va.w, acc[3]);
            acc[4] = fmaf(kl, vb.x, acc[4]); acc[5] = fmaf(kl, vb.y, acc[5]);
            acc[6] = fmaf(kl, vb.z, acc[6]); acc[7] = fmaf(kl, vb.w, acc[7]);
        }
        __syncthreads();
    }
    float* Sp = &g_S[(((b * H_ + h) * NCH + chunk) * LH + l) * DH + d0];
    *(float4*)Sp       = make_float4(acc[0], acc[1], acc[2], acc[3]);
    *(float4*)(Sp + 4) = make_float4(acc[4], acc[5], acc[6], acc[7]);
}
__global__ void state_p2()
{
    int bh = blockIdx.x, tid = threadIdx.x;
    float4 run = make_float4(0, 0, 0, 0);
    for (int c = 0; c < NCH; c++) {
        float4* p = (float4*)&g_S[(size_t)(bh * NCH + c) * (LH * DH) + tid * 4];
        float4 v = *p;
        *p = run;
        run.x += v.x; run.y += v.y; run.z += v.z; run.w += v.w;
    }
}
__global__ __launch_bounds__(64) void scan_p3()
{
    int chunk = blockIdx.x, h = blockIdx.y, b = blockIdx.z;
    int tid = threadIdx.x;
    __shared__ float ke_s[16][16];
    __shared__ float w_s[16][16];
    __shared__ float v_s[16][64];
    float carry[16];
    const float* Sp = &g_S[(size_t)((b * H_ + h) * NCH + chunk) * (LH * DH)];
#pragma unroll
    for (int l = 0; l < 16; l++) carry[l] = Sp[l * 64 + tid];
    int t0 = chunk * CSZ;

    for (int tt = 0; tt < CSZ; tt += 16) {
#pragma unroll
        for (int r = 0; r < 4; r++) {
            int f = r * 64 + tid, tr = f >> 4, li = f & 15;
            int src = (b * T_ + t0 + tt + tr) * L_ + h * LH + li;
            ke_s[tr][li] = g_K[src];
            w_s[tr][li]  = g_Q[src];
        }
#pragma unroll
        for (int r = 0; r < 4; r++) {
            int f = r * 64 + tid, tr = f >> 4, dq = f & 15;
            *(float4*)&v_s[tr][dq * 4] =
                *(const float4*)&g_V[(b * T_ + t0 + tt + tr) * D_ + h * DH + dq * 4];
        }
        __syncthreads();
#pragma unroll
        for (int k = 0; k < 16; k++) {
            float v = v_s[k][tid];
            float4 ke0 = *(const float4*)&ke_s[k][0];
            float4 ke1 = *(const float4*)&ke_s[k][4];
            float4 ke2 = *(const float4*)&ke_s[k][8];
            float4 ke3 = *(const float4*)&ke_s[k][12];
            float4 w0 = *(const float4*)&w_s[k][0];
            float4 w1 = *(const float4*)&w_s[k][4];
            float4 w2 = *(const float4*)&w_s[k][8];
            float4 w3 = *(const float4*)&w_s[k][12];
            float y = 0.f;
            carry[0]  = fmaf(ke0.x, v, carry[0]);  y = fmaf(w0.x, carry[0],  y);
            carry[1]  = fmaf(ke0.y, v, carry[1]);  y = fmaf(w0.y, carry[1],  y);
            carry[2]  = fmaf(ke0.z, v, carry[2]);  y = fmaf(w0.z, carry[2],  y);
            carry[3]  = fmaf(ke0.w, v, carry[3]);  y = fmaf(w0.w, carry[3],  y);
            carry[4]  = fmaf(ke1.x, v, carry[4]);  y = fmaf(w1.x, carry[4],  y);
            carry[5]  = fmaf(ke1.y, v, carry[5]);  y = fmaf(w1.y, carry[5],  y);
            carry[6]  = fmaf(ke1.z, v, carry[6]);  y = fmaf(w1.z, carry[6],  y);
            carry[7]  = fmaf(ke1.w, v, carry[7]);  y = fmaf(w1.w, carry[7],  y);
            carry[8]  = fmaf(ke2.x, v, carry[8]);  y = fmaf(w2.x, carry[8],  y);
            carry[9]  = fmaf(ke2.y, v, carry[9]);  y = fmaf(w2.y, carry[9],  y);
            carry[10] = fmaf(ke2.z, v, carry[10]); y = fmaf(w2.z, carry[10], y);
            carry[11] = fmaf(ke2.w, v, carry[11]); y = fmaf(w2.w, carry[11], y);
            carry[12] = fmaf(ke3.x, v, carry[12]); y = fmaf(w3.x, carry[12], y);
            carry[13] = fmaf(ke3.y, v, carry[13]); y = fmaf(w3.y, carry[13], y);
            carry[14] = fmaf(ke3.z, v, carry[14]); y = fmaf(w3.z, carry[14], y);
            carry[15] = fmaf(ke3.w, v, carry[15]); y = fmaf(w3.w, carry[15], y);
            g_y[(b * T_ + t0 + tt + k) * D_ + h * DH + tid] = y;
        }
        __syncthreads();
    }
}

// ============================================================
// permutation (emits bf16 hi/lo for the O GEMM)
// ============================================================
__global__ __launch_bounds__(256) void transpose_k()
{
    int t8 = blockIdx.x, b = blockIdx.y;
    int tid = threadIdx.x;
    __shared__ float ys[8][512];
#pragma unroll
    for (int r = 0; r < 4; r++) {
        int f = r * 256 + tid, tr = f >> 7, c4 = f & 127;
        *(float4*)&ys[tr][c4 * 4] =
            *(const float4*)&g_y[(size_t)(b * T_ + t8 * 8 + tr) * D_ + c4 * 4];
    }
    __syncthreads();
#pragma unroll
    for (int r = 0; r < 2; r++) {
        int p = r * 256 + tid;
        int k = p >> 6, dh = p & 63;
        unsigned short hv[8], lv[8];
#pragma unroll
        for (int hh = 0; hh < 8; hh++) split2(ys[k][hh * 64 + dh], hv[hh], lv[hh]);
        int bp = dh >> 3, e = dh & 7;
        size_t didx = (size_t)bp * (T_ * D_) + (size_t)(e * 512 + t8) * D_ + k * 64 + b * 8;
        *(uint4*)(g_Yh + didx) = *(uint4*)hv;
        *(uint4*)(g_Yl + didx) = *(uint4*)lv;
    }
}

// ============================================================
extern "C" void kernel_launch(void* const* d_in, const int* in_sizes, int n_in,
                              void* d_out, int out_size)
{
    const float* X  = (const float*)d_in[0];
    const float* Wk = (const float*)d_in[1];
    const float* Wq = (const float*)d_in[2];
    const float* Wv = (const float*)d_in[3];
    const float* Wo = (const float*)d_in[4];
    float* out = (float*)d_out;

    float *pV;
    unsigned short *pXh, *pXl, *pYh, *pYl;
    unsigned short *pWqkh, *pWqkl, *pWvh, *pWvl, *pWoh, *pWol;
    cudaGetSymbolAddress((void**)&pV, g_V);
    cudaGetSymbolAddress((void**)&pXh, g_Xh);
    cudaGetSymbolAddress((void**)&pXl, g_Xl);
    cudaGetSymbolAddress((void**)&pYh, g_Yh);
    cudaGetSymbolAddress((void**)&pYl, g_Yl);
    cudaGetSymbolAddress((void**)&pWqkh, g_Wqkh);
    cudaGetSymbolAddress((void**)&pWqkl, g_Wqkl);
    cudaGetSymbolAddress((void**)&pWvh, g_Wvh);
    cudaGetSymbolAddress((void**)&pWvl, g_Wvl);
    cudaGetSymbolAddress((void**)&pWoh, g_Woh);
    cudaGetSymbolAddress((void**)&pWol, g_Wol);

    cudaFuncSetAttribute(gemm_mma<0>, cudaFuncAttributeMaxDynamicSharedMemorySize, GEMM_SMEM);
    cudaFuncSetAttribute(gemm_mma<1>, cudaFuncAttributeMaxDynamicSharedMemorySize, GEMM_SMEM);

    // conversions
    conv_X<<<M_ * D_ / 1024, 256>>>(X);
    conv_Wt<<<(D_ * L_) / 256, 256>>>(Wq, pWqkh, pWqkl, L_, 0);
    conv_Wt<<<(D_ * L_) / 256, 256>>>(Wk, pWqkh, pWqkl, L_, L_);
    conv_Wt<<<(D_ * D_) / 256, 256>>>(Wv, pWvh, pWvl, D_, 0);
    conv_Wt<<<(D_ * D_) / 256, 256>>>(Wo, pWoh, pWol, D_, 0);

    // fused Q+K projection (2-term) and V projection (3-term)
    gemm_mma<1><<<dim3(2, 256), 256, GEMM_SMEM>>>(pXh, pXl, pWqkh, pWqkl, nullptr, 256);
    gemm_mma<0><<<dim3(4, 256), 256, GEMM_SMEM>>>(pXh, pXl, pWvh, pWvl, pV, D_);

    // alpha cumsum + fused softmax/normalize
    alpha_p1<<<dim3(NCH, B_), 128>>>();
    alpha_p2<<<B_, 128>>>();
    alpha_p3<<<dim3(NCH, B_), 128>>>();

    // chunk-parallel state scan
    state_p1<<<dim3(NCH, H_, B_), 128>>>();
    state_p2<<<B_ * H_, 256>>>();
    scan_p3<<<dim3(NCH, H_, B_), 64>>>();

    // permutation + output projection (3-term)
    transpose_k<<<dim3(T_ / 8, B_), 256>>>();
    gemm_mma<0><<<dim3(4, 256), 256, GEMM_SMEM>>>(pYh, pYl, pWoh, pWol, out, D_);
}

// round 7
// speedup vs baseline: 2.3470x; 1.2740x over previous
#include <cuda_runtime.h>
#include <cuda_fp16.h>
#include <cstdint>

#define T_  4096
#define B_  8
#define D_  512
#define L_  128
#define H_  8
#define DH  64
#define LH  16
#define M_  (B_*T_)
#define NCH 32
#define CSZ 128

// ---------------- scratch ----------------
__device__ float g_Q[M_*L_];
__device__ float g_K[M_*L_];
__device__ float g_V[M_*D_];
__device__ float g_csum[B_*NCH*L_];
__device__ float g_S[B_*H_*NCH*LH*DH];
__device__ unsigned short g_Xh[M_*D_];       // X in fp16 (hi only)
__device__ unsigned short g_yh[M_*D_];       // scan output, fp16, natural layout
__device__ unsigned short g_Yph[M_*D_];      // permuted scan output, fp16
__device__ unsigned short g_Wbh[3*L_*D_ + 0], g_Wbl[3*L_*D_ + 0]; // unused guard
__device__ unsigned short g_Wqkvh[(2*L_+D_)*D_], g_Wqkvl[(2*L_+D_)*D_]; // [768][512]
__device__ unsigned short g_Woh[D_*D_], g_Wol[D_*D_];

// ---------------- portable PTX helpers ----------------
__device__ __forceinline__ uint32_t smem_u32(const void* p) {
    uint32_t a;
    asm("{ .reg .u64 t; cvta.to.shared.u64 t, %1; cvt.u32.u64 %0, t; }" : "=r"(a) : "l"(p));
    return a;
}
__device__ __forceinline__ void ldsm4(uint32_t* r, uint32_t addr) {
    asm volatile("ldmatrix.sync.aligned.m8n8.x4.shared.b16 {%0,%1,%2,%3}, [%4];"
                 : "=r"(r[0]), "=r"(r[1]), "=r"(r[2]), "=r"(r[3]) : "r"(addr));
}
__device__ __forceinline__ void mma16816(float* d, const uint32_t* a, const uint32_t* b) {
    asm volatile("mma.sync.aligned.m16n8k16.row.col.f32.f16.f16.f32 "
                 "{%0,%1,%2,%3}, {%4,%5,%6,%7}, {%8,%9}, {%0,%1,%2,%3};"
                 : "+f"(d[0]), "+f"(d[1]), "+f"(d[2]), "+f"(d[3])
                 : "r"(a[0]), "r"(a[1]), "r"(a[2]), "r"(a[3]), "r"(b[0]), "r"(b[1]));
}
#define CP_ASYNC16(dst, src) \
    asm volatile("cp.async.cg.shared.global [%0], [%1], 16;" :: "r"(dst), "l"(src))
#define CP_COMMIT() asm volatile("cp.async.commit_group;" ::: "memory")
#define CP_WAIT(n)  asm volatile("cp.async.wait_group %0;" :: "n"(n) : "memory")

// ============================================================
// fp16 2-term GEMM via mma.sync: C = Ah @ (Bh + Bl)^T, fp32 acc.
// Tile 128x128, BK=32, 256 thr (2x4 warps, 64x32 warp tile).
// Smem: 3 matrices (Ah,Bh,Bl), 80B row stride, double-buffered.
// MODE 1: QKV fused epilogue (bx 0->Q raw, 1->K exp(0.125*), >=2->V)
// MODE 0: plain C[M,512] (O projection to d_out)
// ============================================================
#define ROWB 80
#define MATB (128 * ROWB)
#define BUFB (3 * MATB)            // 30720
#define GEMM_SMEM (2 * BUFB)       // 61440

__device__ __forceinline__ void issue_loads(const unsigned short* ah,
                                            const unsigned short* bh,
                                            const unsigned short* bl,
                                            int k0, uint32_t smbuf, int tid)
{
#pragma unroll
    for (int half = 0; half < 2; half++) {
        int c = half * 256 + tid;
        int r = c >> 2, s = c & 3;
        uint32_t soff = (uint32_t)(r * ROWB + s * 16);
        CP_ASYNC16(smbuf + 0 * MATB + soff, ah + (size_t)r * 512 + k0 + s * 8);
        CP_ASYNC16(smbuf + 1 * MATB + soff, bh + (size_t)r * 512 + k0 + s * 8);
        CP_ASYNC16(smbuf + 2 * MATB + soff, bl + (size_t)r * 512 + k0 + s * 8);
    }
}

template<int MODE>
__global__ __launch_bounds__(256, 2) void gemm_mma(const unsigned short* __restrict__ Ah,
                                                   const unsigned short* __restrict__ Bh,
                                                   const unsigned short* __restrict__ Bl,
                                                   float* __restrict__ C)
{
    extern __shared__ char sm[];
    const int tid = threadIdx.x;
    const int wid = tid >> 5, lane = tid & 31;
    const int wm = wid >> 2, wn = wid & 3;
    const int m0 = blockIdx.y * 128;
    const int n0 = blockIdx.x * 128;
    const uint32_t smb = smem_u32(sm);

    const unsigned short* ah = Ah + (size_t)m0 * 512;
    const unsigned short* bh = Bh + (size_t)n0 * 512;
    const unsigned short* bl = Bl + (size_t)n0 * 512;

    float acc[4][4][4];
#pragma unroll
    for (int i = 0; i < 4; i++)
#pragma unroll
        for (int j = 0; j < 4; j++)
#pragma unroll
            for (int e = 0; e < 4; e++) acc[i][j][e] = 0.f;

    const uint32_t a_lane = (uint32_t)((wm * 64 + (lane & 15)) * ROWB + (lane >> 4) * 16);
    const uint32_t b_lane = (uint32_t)((wn * 32 + (lane & 15)) * ROWB + (lane >> 4) * 16);

    issue_loads(ah, bh, bl, 0, smb, tid);
    CP_COMMIT();

    const int NIT = 512 / 32;
    for (int ki = 0; ki < NIT; ki++) {
        const uint32_t buf = smb + (uint32_t)(ki & 1) * BUFB;
        if (ki + 1 < NIT) {
            issue_loads(ah, bh, bl, (ki + 1) * 32, smb + (uint32_t)((ki + 1) & 1) * BUFB, tid);
            CP_COMMIT();
            CP_WAIT(1);
        } else {
            CP_WAIT(0);
        }
        __syncthreads();

#pragma unroll
        for (int ks = 0; ks < 2; ks++) {
            const uint32_t koff = (uint32_t)(ks * 32);
            uint32_t fBh[4][2], fBl[4][2];
#pragma unroll
            for (int p = 0; p < 2; p++) {
                uint32_t r[4];
                ldsm4(r, buf + 1 * MATB + b_lane + (uint32_t)(p * 16 * ROWB) + koff);
                fBh[2 * p][0] = r[0]; fBh[2 * p][1] = r[2];
                fBh[2 * p + 1][0] = r[1]; fBh[2 * p + 1][1] = r[3];
                ldsm4(r, buf + 2 * MATB + b_lane + (uint32_t)(p * 16 * ROWB) + koff);
                fBl[2 * p][0] = r[0]; fBl[2 * p][1] = r[2];
                fBl[2 * p + 1][0] = r[1]; fBl[2 * p + 1][1] = r[3];
            }
#pragma unroll
            for (int mf = 0; mf < 4; mf++) {
                uint32_t fAh[4];
                ldsm4(fAh, buf + 0 * MATB + a_lane + (uint32_t)(mf * 16 * ROWB) + koff);
#pragma unroll
                for (int nf = 0; nf < 4; nf++) {
                    mma16816(acc[mf][nf], fAh, fBh[nf]);
                    mma16816(acc[mf][nf], fAh, fBl[nf]);
                }
            }
        }
        __syncthreads();
    }

    // epilogue
    const int rr = lane >> 2, cc = (lane & 3) * 2;
    float* Cout;
    int cstride, colbase;
    bool do_exp = false;
    if (MODE == 1) {
        if (blockIdx.x == 0)      { Cout = g_Q; cstride = L_;  colbase = 0; }
        else if (blockIdx.x == 1) { Cout = g_K; cstride = L_;  colbase = 0; do_exp = true; }
        else                      { Cout = g_V; cstride = D_;  colbase = (blockIdx.x - 2) * 128; }
    } else {
        Cout = C; cstride = D_; colbase = n0;
    }
#pragma unroll
    for (int mf = 0; mf < 4; mf++) {
#pragma unroll
        for (int nf = 0; nf < 4; nf++) {
            int row = m0 + wm * 64 + mf * 16 + rr;
            int col = colbase + wn * 32 + nf * 8 + cc;
            float d0 = acc[mf][nf][0], d1 = acc[mf][nf][1];
            float d2 = acc[mf][nf][2], d3 = acc[mf][nf][3];
            if (MODE == 1 && do_exp) {
                d0 = __expf(0.125f * d0); d1 = __expf(0.125f * d1);
                d2 = __expf(0.125f * d2); d3 = __expf(0.125f * d3);
            }
            *(float2*)(Cout + (size_t)row * cstride + col)       = make_float2(d0, d1);
            *(float2*)(Cout + (size_t)(row + 8) * cstride + col) = make_float2(d2, d3);
        }
    }
}

// ============================================================
// conversions (fp16)
// ============================================================
__device__ __forceinline__ void split2h(float x, unsigned short& h, unsigned short& l) {
    __half hb = __float2half(x);
    __half lb = __float2half(x - __half2float(hb));
    h = __half_as_ushort(hb);
    l = __half_as_ushort(lb);
}
__global__ void conv_X(const float* __restrict__ X)
{
    int i = blockIdx.x * 256 + threadIdx.x;
    float4 v = ((const float4*)X)[i];
    ushort4 h;
    h.x = __half_as_ushort(__float2half(v.x));
    h.y = __half_as_ushort(__float2half(v.y));
    h.z = __half_as_ushort(__float2half(v.z));
    h.w = __half_as_ushort(__float2half(v.w));
    ((ushort4*)g_Xh)[i] = h;
}
// W[512][N] -> dst rows [N][512] (hi/lo fp16) at row offset roff
__global__ void conv_Wt(const float* __restrict__ W, unsigned short* __restrict__ Th,
                        unsigned short* __restrict__ Tl, int N, int roff)
{
    int id = blockIdx.x * 256 + threadIdx.x;
    int n = id % N, k = id / N;
    unsigned short h, l;
    split2h(W[id], h, l);
    Th[(roff + n) * 512 + k] = h;
    Tl[(roff + n) * 512 + k] = l;
}

// ============================================================
// alpha cumsum; p3 fuses softmax(Q/8) and w = softmax/alpha
// ============================================================
__global__ void alpha_p1()
{
    int chunk = blockIdx.x, b = blockIdx.y, l = threadIdx.x;
    float s = 0.f;
    int base = (b * T_ + chunk * CSZ) * L_ + l;
    for (int i = 0; i < CSZ; i++) s += g_K[base + i * L_];
    g_csum[(b * NCH + chunk) * L_ + l] = s;
}
__global__ void alpha_p2()
{
    int b = blockIdx.x, l = threadIdx.x;
    float run = 0.f;
    for (int c = 0; c < NCH; c++) {
        int idx = (b * NCH + c) * L_ + l;
        float v = g_csum[idx];
        g_csum[idx] = run;
        run += v;
    }
}
__global__ void alpha_p3()
{
    int chunk = blockIdx.x, b = blockIdx.y, l = threadIdx.x;
    float a = g_csum[(b * NCH + chunk) * L_ + l];
    int base = (b * T_ + chunk * CSZ) * L_ + l;
    for (int i = 0; i < CSZ; i++) {
        int idx = base + i * L_;
        a += g_K[idx];
        float q = g_Q[idx] * 0.125f;
        float m = q;
#pragma unroll
        for (int s = 8; s >= 1; s >>= 1)
            m = fmaxf(m, __shfl_xor_sync(0xffffffffu, m, s));
        float e = __expf(q - m);
        float sum = e;
#pragma unroll
        for (int s = 8; s >= 1; s >>= 1)
            sum += __shfl_xor_sync(0xffffffffu, sum, s);
        g_Q[idx] = __fdividef(e, sum * a);
    }
}

// ============================================================
// scan passes
// ============================================================
__global__ __launch_bounds__(128) void state_p1()
{
    int chunk = blockIdx.x, h = blockIdx.y, b = blockIdx.z;
    int tid = threadIdx.x;
    int l = tid >> 3, d0 = (tid & 7) * 8;
    __shared__ float ke_s[16][16];
    __shared__ float v_s[16][64];
    float acc[8] = {0, 0, 0, 0, 0, 0, 0, 0};
    int t0 = chunk * CSZ;
    for (int tt = 0; tt < CSZ; tt += 16) {
#pragma unroll
        for (int r = 0; r < 2; r++) {
            int f = r * 128 + tid, tr = f >> 4, li = f & 15;
            ke_s[tr][li] = g_K[(b * T_ + t0 + tt + tr) * L_ + h * LH + li];
        }
#pragma unroll
        for (int r = 0; r < 2; r++) {
            int f = r * 128 + tid, tr = f >> 4, dq = f & 15;
            *(float4*)&v_s[tr][dq * 4] =
                *(const float4*)&g_V[(b * T_ + t0 + tt + tr) * D_ + h * DH + dq * 4];
        }
        __syncthreads();
#pragma unroll
        for (int k = 0; k < 16; k++) {
            float kl = ke_s[k][l];
            float4 va = *(const float4*)&v_s[k][d0];
            float4 vb = *(const float4*)&v_s[k][d0 + 4];
            acc[0] = fmaf(kl, va.x, acc[0]); acc[1] = fmaf(kl, va.y, acc[1]);
            acc[2] = fmaf(kl, va.z, acc[2]); acc[3] = fmaf(kl, va.w, acc[3]);
            acc[4] = fmaf(kl, vb.x, acc[4]); acc[5] = fmaf(kl, vb.y, acc[5]);
            acc[6] = fmaf(kl, vb.z, acc[6]); acc[7] = fmaf(kl, vb.w, acc[7]);
        }
        __syncthreads();
    }
    float* Sp = &g_S[(((b * H_ + h) * NCH + chunk) * LH + l) * DH + d0];
    *(float4*)Sp       = make_float4(acc[0], acc[1], acc[2], acc[3]);
    *(float4*)(Sp + 4) = make_float4(acc[4], acc[5], acc[6], acc[7]);
}
__global__ void state_p2()
{
    int bh = blockIdx.x, tid = threadIdx.x;
    float4 run = make_float4(0, 0, 0, 0);
    for (int c = 0; c < NCH; c++) {
        float4* p = (float4*)&g_S[(size_t)(bh * NCH + c) * (LH * DH) + tid * 4];
        float4 v = *p;
        *p = run;
        run.x += v.x; run.y += v.y; run.z += v.z; run.w += v.w;
    }
}
__global__ __launch_bounds__(64) void scan_p3()
{
    int chunk = blockIdx.x, h = blockIdx.y, b = blockIdx.z;
    int tid = threadIdx.x;
    __shared__ float ke_s[16][16];
    __shared__ float w_s[16][16];
    __shared__ float v_s[16][64];
    float carry[16];
    const float* Sp = &g_S[(size_t)((b * H_ + h) * NCH + chunk) * (LH * DH)];
#pragma unroll
    for (int l = 0; l < 16; l++) carry[l] = Sp[l * 64 + tid];
    int t0 = chunk * CSZ;

    for (int tt = 0; tt < CSZ; tt += 16) {
#pragma unroll
        for (int r = 0; r < 4; r++) {
            int f = r * 64 + tid, tr = f >> 4, li = f & 15;
            int src = (b * T_ + t0 + tt + tr) * L_ + h * LH + li;
            ke_s[tr][li] = g_K[src];
            w_s[tr][li]  = g_Q[src];
        }
#pragma unroll
        for (int r = 0; r < 4; r++) {
            int f = r * 64 + tid, tr = f >> 4, dq = f & 15;
            *(float4*)&v_s[tr][dq * 4] =
                *(const float4*)&g_V[(b * T_ + t0 + tt + tr) * D_ + h * DH + dq * 4];
        }
        __syncthreads();
#pragma unroll
        for (int k = 0; k < 16; k++) {
            float v = v_s[k][tid];
            float4 ke0 = *(const float4*)&ke_s[k][0];
            float4 ke1 = *(const float4*)&ke_s[k][4];
            float4 ke2 = *(const float4*)&ke_s[k][8];
            float4 ke3 = *(const float4*)&ke_s[k][12];
            float4 w0 = *(const float4*)&w_s[k][0];
            float4 w1 = *(const float4*)&w_s[k][4];
            float4 w2 = *(const float4*)&w_s[k][8];
            float4 w3 = *(const float4*)&w_s[k][12];
            float y = 0.f;
            carry[0]  = fmaf(ke0.x, v, carry[0]);  y = fmaf(w0.x, carry[0],  y);
            carry[1]  = fmaf(ke0.y, v, carry[1]);  y = fmaf(w0.y, carry[1],  y);
            carry[2]  = fmaf(ke0.z, v, carry[2]);  y = fmaf(w0.z, carry[2],  y);
            carry[3]  = fmaf(ke0.w, v, carry[3]);  y = fmaf(w0.w, carry[3],  y);
            carry[4]  = fmaf(ke1.x, v, carry[4]);  y = fmaf(w1.x, carry[4],  y);
            carry[5]  = fmaf(ke1.y, v, carry[5]);  y = fmaf(w1.y, carry[5],  y);
            carry[6]  = fmaf(ke1.z, v, carry[6]);  y = fmaf(w1.z, carry[6],  y);
            carry[7]  = fmaf(ke1.w, v, carry[7]);  y = fmaf(w1.w, carry[7],  y);
            carry[8]  = fmaf(ke2.x, v, carry[8]);  y = fmaf(w2.x, carry[8],  y);
            carry[9]  = fmaf(ke2.y, v, carry[9]);  y = fmaf(w2.y, carry[9],  y);
            carry[10] = fmaf(ke2.z, v, carry[10]); y = fmaf(w2.z, carry[10], y);
            carry[11] = fmaf(ke2.w, v, carry[11]); y = fmaf(w2.w, carry[11], y);
            carry[12] = fmaf(ke3.x, v, carry[12]); y = fmaf(w3.x, carry[12], y);
            carry[13] = fmaf(ke3.y, v, carry[13]); y = fmaf(w3.y, carry[13], y);
            carry[14] = fmaf(ke3.z, v, carry[14]); y = fmaf(w3.z, carry[14], y);
            carry[15] = fmaf(ke3.w, v, carry[15]); y = fmaf(w3.w, carry[15], y);
            g_yh[(b * T_ + t0 + tt + k) * D_ + h * DH + tid] =
                __half_as_ushort(__float2half(y));
        }
        __syncthreads();
    }
}

// ============================================================
// permutation, pure fp16 shuffle (no split needed)
// ============================================================
__global__ __launch_bounds__(256) void transpose_k()
{
    int t8 = blockIdx.x, b = blockIdx.y;
    int tid = threadIdx.x;
    __shared__ unsigned short ys[8][512];
#pragma unroll
    for (int r = 0; r < 2; r++) {
        int f = r * 256 + tid, tr = f >> 6, c8 = f & 63;
        *(uint4*)&ys[tr][c8 * 8] =
            *(const uint4*)&g_yh[(size_t)(b * T_ + t8 * 8 + tr) * D_ + c8 * 8];
    }
    __syncthreads();
#pragma unroll
    for (int r = 0; r < 2; r++) {
        int p = r * 256 + tid;
        int k = p >> 6, dh = p & 63;
        unsigned short v[8];
#pragma unroll
        for (int hh = 0; hh < 8; hh++) v[hh] = ys[k][hh * 64 + dh];
        int bp = dh >> 3, e = dh & 7;
        size_t didx = (size_t)bp * (T_ * D_) + (size_t)(e * 512 + t8) * D_ + k * 64 + b * 8;
        *(uint4*)(g_Yph + didx) = *(uint4*)v;
    }
}

// ============================================================
extern "C" void kernel_launch(void* const* d_in, const int* in_sizes, int n_in,
                              void* d_out, int out_size)
{
    const float* X  = (const float*)d_in[0];
    const float* Wk = (const float*)d_in[1];
    const float* Wq = (const float*)d_in[2];
    const float* Wv = (const float*)d_in[3];
    const float* Wo = (const float*)d_in[4];
    float* out = (float*)d_out;

    unsigned short *pXh, *pYph, *pWqkvh, *pWqkvl, *pWoh, *pWol;
    cudaGetSymbolAddress((void**)&pXh, g_Xh);
    cudaGetSymbolAddress((void**)&pYph, g_Yph);
    cudaGetSymbolAddress((void**)&pWqkvh, g_Wqkvh);
    cudaGetSymbolAddress((void**)&pWqkvl, g_Wqkvl);
    cudaGetSymbolAddress((void**)&pWoh, g_Woh);
    cudaGetSymbolAddress((void**)&pWol, g_Wol);

    cudaFuncSetAttribute(gemm_mma<0>, cudaFuncAttributeMaxDynamicSharedMemorySize, GEMM_SMEM);
    cudaFuncSetAttribute(gemm_mma<1>, cudaFuncAttributeMaxDynamicSharedMemorySize, GEMM_SMEM);

    // conversions (X hi-only fp16; weights hi/lo fp16, QKV concatenated)
    conv_X<<<M_ * D_ / 1024, 256>>>(X);
    conv_Wt<<<(D_ * L_) / 256, 256>>>(Wq, pWqkvh, pWqkvl, L_, 0);
    conv_Wt<<<(D_ * L_) / 256, 256>>>(Wk, pWqkvh, pWqkvl, L_, L_);
    conv_Wt<<<(D_ * D_) / 256, 256>>>(Wv, pWqkvh, pWqkvl, D_, 2 * L_);
    conv_Wt<<<(D_ * D_) / 256, 256>>>(Wo, pWoh, pWol, D_, 0);

    // fused QKV projection (single launch, 2-term fp16)
    gemm_mma<1><<<dim3(6, 256), 256, GEMM_SMEM>>>(pXh, pWqkvh, pWqkvl, nullptr);

    // alpha cumsum + fused softmax/normalize
    alpha_p1<<<dim3(NCH, B_), 128>>>();
    alpha_p2<<<B_, 128>>>();
    alpha_p3<<<dim3(NCH, B_), 128>>>();

    // chunk-parallel state scan
    state_p1<<<dim3(NCH, H_, B_), 128>>>();
    state_p2<<<B_ * H_, 256>>>();
    scan_p3<<<dim3(NCH, H_, B_), 64>>>();

    // permutation + output projection (2-term fp16)
    transpose_k<<<dim3(T_ / 8, B_), 256>>>();
    gemm_mma<0><<<dim3(4, 256), 256, GEMM_SMEM>>>(pYph, pWoh, pWol, out);
}

// round 8
// speedup vs baseline: 2.7024x; 1.1514x over previous
#include <cuda_runtime.h>
#include <cuda_fp16.h>
#include <cstdint>

#define T_  4096
#define B_  8
#define D_  512
#define L_  128
#define H_  8
#define DH  64
#define LH  16
#define M_  (B_*T_)
#define NCH 64          // state-scan chunks
#define CSZ 64          // T_/NCH
#define NCA 128         // alpha chunks
#define CSA 32          // T_/NCA

// ---------------- scratch ----------------
__device__ float g_Q[M_*L_];
__device__ float g_K[M_*L_];
__device__ float g_V[M_*D_];
__device__ float g_csum[B_*NCA*L_];
__device__ float g_S[B_*H_*NCH*LH*DH];
__device__ unsigned short g_Xh[M_*D_];       // X fp16
__device__ unsigned short g_yh[M_*D_];       // scan out fp16 natural
__device__ unsigned short g_Yph[M_*D_];      // permuted fp16
__device__ unsigned short g_Wqkvh[(2*L_+D_)*D_], g_Wqkvl[(2*L_+D_)*D_];
__device__ unsigned short g_Woh[D_*D_], g_Wol[D_*D_];

// ---------------- PTX helpers ----------------
__device__ __forceinline__ uint32_t smem_u32(const void* p) {
    uint32_t a;
    asm("{ .reg .u64 t; cvta.to.shared.u64 t, %1; cvt.u32.u64 %0, t; }" : "=r"(a) : "l"(p));
    return a;
}
__device__ __forceinline__ void ldsm4(uint32_t* r, uint32_t addr) {
    asm volatile("ldmatrix.sync.aligned.m8n8.x4.shared.b16 {%0,%1,%2,%3}, [%4];"
                 : "=r"(r[0]), "=r"(r[1]), "=r"(r[2]), "=r"(r[3]) : "r"(addr));
}
__device__ __forceinline__ void mma16816(float* d, const uint32_t* a, const uint32_t* b) {
    asm volatile("mma.sync.aligned.m16n8k16.row.col.f32.f16.f16.f32 "
                 "{%0,%1,%2,%3}, {%4,%5,%6,%7}, {%8,%9}, {%0,%1,%2,%3};"
                 : "+f"(d[0]), "+f"(d[1]), "+f"(d[2]), "+f"(d[3])
                 : "r"(a[0]), "r"(a[1]), "r"(a[2]), "r"(a[3]), "r"(b[0]), "r"(b[1]));
}
#define CP_ASYNC16(dst, src) \
    asm volatile("cp.async.cg.shared.global [%0], [%1], 16;" :: "r"(dst), "l"(src))
#define CP_COMMIT() asm volatile("cp.async.commit_group;" ::: "memory")
#define CP_WAIT(n)  asm volatile("cp.async.wait_group %0;" :: "n"(n) : "memory")

// ============================================================
// fp16 GEMM via mma.sync, fp32 acc. Tile 128x128, BK=32, 256 thr.
// B-term count is runtime per-CTA: MODE 1, blockIdx.x<2 (Q,K) -> 1-term.
// MODE 1: fused QKV epi (bx0 Q raw, bx1 K exp(0.125*), bx>=2 V)
// MODE 0: C[M,512] (O projection), always 2-term.
// ============================================================
#define ROWB 80
#define MATB (128 * ROWB)
#define BUFB (3 * MATB)
#define GEMM_SMEM (2 * BUFB)

__device__ __forceinline__ void issue_loads(const unsigned short* ah,
                                            const unsigned short* bh,
                                            const unsigned short* bl,
                                            int k0, uint32_t smbuf, int tid, bool bl_on)
{
#pragma unroll
    for (int half = 0; half < 2; half++) {
        int c = half * 256 + tid;
        int r = c >> 2, s = c & 3;
        uint32_t soff = (uint32_t)(r * ROWB + s * 16);
        CP_ASYNC16(smbuf + 0 * MATB + soff, ah + (size_t)r * 512 + k0 + s * 8);
        CP_ASYNC16(smbuf + 1 * MATB + soff, bh + (size_t)r * 512 + k0 + s * 8);
        if (bl_on)
            CP_ASYNC16(smbuf + 2 * MATB + soff, bl + (size_t)r * 512 + k0 + s * 8);
    }
}

template<int MODE>
__global__ __launch_bounds__(256, 2) void gemm_mma(const unsigned short* __restrict__ Ah,
                                                   const unsigned short* __restrict__ Bh,
                                                   const unsigned short* __restrict__ Bl,
                                                   float* __restrict__ C)
{
    extern __shared__ char sm[];
    const int tid = threadIdx.x;
    const int wid = tid >> 5, lane = tid & 31;
    const int wm = wid >> 2, wn = wid & 3;
    const int m0 = blockIdx.y * 128;
    const int n0 = blockIdx.x * 128;
    const uint32_t smb = smem_u32(sm);
    const bool two = (MODE == 0) || (blockIdx.x >= 2);

    const unsigned short* ah = Ah + (size_t)m0 * 512;
    const unsigned short* bh = Bh + (size_t)n0 * 512;
    const unsigned short* bl = Bl + (size_t)n0 * 512;

    float acc[4][4][4];
#pragma unroll
    for (int i = 0; i < 4; i++)
#pragma unroll
        for (int j = 0; j < 4; j++)
#pragma unroll
            for (int e = 0; e < 4; e++) acc[i][j][e] = 0.f;

    const uint32_t a_lane = (uint32_t)((wm * 64 + (lane & 15)) * ROWB + (lane >> 4) * 16);
    const uint32_t b_lane = (uint32_t)((wn * 32 + (lane & 15)) * ROWB + (lane >> 4) * 16);

    issue_loads(ah, bh, bl, 0, smb, tid, two);
    CP_COMMIT();

    const int NIT = 512 / 32;
    for (int ki = 0; ki < NIT; ki++) {
        const uint32_t buf = smb + (uint32_t)(ki & 1) * BUFB;
        if (ki + 1 < NIT) {
            issue_loads(ah, bh, bl, (ki + 1) * 32, smb + (uint32_t)((ki + 1) & 1) * BUFB, tid, two);
            CP_COMMIT();
            CP_WAIT(1);
        } else {
            CP_WAIT(0);
        }
        __syncthreads();

#pragma unroll
        for (int ks = 0; ks < 2; ks++) {
            const uint32_t koff = (uint32_t)(ks * 32);
            uint32_t fBh[4][2], fBl[4][2];
#pragma unroll
            for (int p = 0; p < 2; p++) {
                uint32_t r[4];
                ldsm4(r, buf + 1 * MATB + b_lane + (uint32_t)(p * 16 * ROWB) + koff);
                fBh[2 * p][0] = r[0]; fBh[2 * p][1] = r[2];
                fBh[2 * p + 1][0] = r[1]; fBh[2 * p + 1][1] = r[3];
                if (two) {
                    ldsm4(r, buf + 2 * MATB + b_lane + (uint32_t)(p * 16 * ROWB) + koff);
                    fBl[2 * p][0] = r[0]; fBl[2 * p][1] = r[2];
                    fBl[2 * p + 1][0] = r[1]; fBl[2 * p + 1][1] = r[3];
                }
            }
#pragma unroll
            for (int mf = 0; mf < 4; mf++) {
                uint32_t fAh[4];
                ldsm4(fAh, buf + 0 * MATB + a_lane + (uint32_t)(mf * 16 * ROWB) + koff);
#pragma unroll
                for (int nf = 0; nf < 4; nf++) {
                    mma16816(acc[mf][nf], fAh, fBh[nf]);
                    if (two) mma16816(acc[mf][nf], fAh, fBl[nf]);
                }
            }
        }
        __syncthreads();
    }

    // epilogue
    const int rr = lane >> 2, cc = (lane & 3) * 2;
    float* Cout;
    int cstride, colbase;
    bool do_exp = false;
    if (MODE == 1) {
        if (blockIdx.x == 0)      { Cout = g_Q; cstride = L_; colbase = 0; }
        else if (blockIdx.x == 1) { Cout = g_K; cstride = L_; colbase = 0; do_exp = true; }
        else                      { Cout = g_V; cstride = D_; colbase = (blockIdx.x - 2) * 128; }
    } else {
        Cout = C; cstride = D_; colbase = n0;
    }
#pragma unroll
    for (int mf = 0; mf < 4; mf++) {
#pragma unroll
        for (int nf = 0; nf < 4; nf++) {
            int row = m0 + wm * 64 + mf * 16 + rr;
            int col = colbase + wn * 32 + nf * 8 + cc;
            float d0 = acc[mf][nf][0], d1 = acc[mf][nf][1];
            float d2 = acc[mf][nf][2], d3 = acc[mf][nf][3];
            if (MODE == 1 && do_exp) {
                d0 = __expf(0.125f * d0); d1 = __expf(0.125f * d1);
                d2 = __expf(0.125f * d2); d3 = __expf(0.125f * d3);
            }
            *(float2*)(Cout + (size_t)row * cstride + col)       = make_float2(d0, d1);
            *(float2*)(Cout + (size_t)(row + 8) * cstride + col) = make_float2(d2, d3);
        }
    }
}

// ============================================================
// conversions
// ============================================================
__device__ __forceinline__ void split2h(float x, unsigned short& h, unsigned short& l) {
    __half hb = __float2half(x);
    __half lb = __float2half(x - __half2float(hb));
    h = __half_as_ushort(hb);
    l = __half_as_ushort(lb);
}
__global__ void conv_X(const float* __restrict__ X)
{
    int i = blockIdx.x * 256 + threadIdx.x;
    float4 v = ((const float4*)X)[i];
    ushort4 h;
    h.x = __half_as_ushort(__float2half(v.x));
    h.y = __half_as_ushort(__float2half(v.y));
    h.z = __half_as_ushort(__float2half(v.z));
    h.w = __half_as_ushort(__float2half(v.w));
    ((ushort4*)g_Xh)[i] = h;
}
// all four W[512][N] -> [N][512] hi/lo transposes in one launch, tiled
__global__ __launch_bounds__(256) void conv_W_all(const float* __restrict__ Wq,
                                                  const float* __restrict__ Wk,
                                                  const float* __restrict__ Wv,
                                                  const float* __restrict__ Wo)
{
    __shared__ float ts[32][33];
    const int z = blockIdx.z;
    const float* W;
    unsigned short *Th, *Tl;
    int N, roff;
    if (z == 0)      { W = Wq; Th = g_Wqkvh; Tl = g_Wqkvl; N = L_;  roff = 0; }
    else if (z == 1) { W = Wk; Th = g_Wqkvh; Tl = g_Wqkvl; N = L_;  roff = L_; }
    else if (z == 2) { W = Wv; Th = g_Wqkvh; Tl = g_Wqkvl; N = D_;  roff = 2 * L_; }
    else             { W = Wo; Th = g_Woh;   Tl = g_Wol;   N = D_;  roff = 0; }
    const int n0 = blockIdx.x * 32, k0 = blockIdx.y * 32;
    if (n0 >= N) return;
    const int tid = threadIdx.x;
#pragma unroll
    for (int i = 0; i < 4; i++) {
        int f = i * 256 + tid;
        int kk = f >> 5, nn = f & 31;
        ts[kk][nn] = W[(size_t)(k0 + kk) * N + n0 + nn];
    }
    __syncthreads();
#pragma unroll
    for (int i = 0; i < 4; i++) {
        int f = i * 256 + tid;
        int nn = f >> 5, kk = f & 31;
        unsigned short h, l;
        split2h(ts[kk][nn], h, l);
        size_t di = (size_t)(roff + n0 + nn) * 512 + k0 + kk;
        Th[di] = h;
        Tl[di] = l;
    }
}

// ============================================================
// alpha cumsum (NCA=128 chunks); p3 fuses softmax + normalize
// ============================================================
__global__ void alpha_p1()
{
    int chunk = blockIdx.x, b = blockIdx.y, l = threadIdx.x;
    float s = 0.f;
    int base = (b * T_ + chunk * CSA) * L_ + l;
    for (int i = 0; i < CSA; i++) s += g_K[base + i * L_];
    g_csum[(b * NCA + chunk) * L_ + l] = s;
}
__global__ void alpha_p2()
{
    int b = blockIdx.x, l = threadIdx.x;
    float run = 0.f;
    for (int c = 0; c < NCA; c++) {
        int idx = (b * NCA + c) * L_ + l;
        float v = g_csum[idx];
        g_csum[idx] = run;
        run += v;
    }
}
__global__ void alpha_p3()
{
    int chunk = blockIdx.x, b = blockIdx.y, l = threadIdx.x;
    float a = g_csum[(b * NCA + chunk) * L_ + l];
    int base = (b * T_ + chunk * CSA) * L_ + l;
    for (int i = 0; i < CSA; i++) {
        int idx = base + i * L_;
        a += g_K[idx];
        float q = g_Q[idx] * 0.125f;
        float m = q;
#pragma unroll
        for (int s = 8; s >= 1; s >>= 1)
            m = fmaxf(m, __shfl_xor_sync(0xffffffffu, m, s));
        float e = __expf(q - m);
        float sum = e;
#pragma unroll
        for (int s = 8; s >= 1; s >>= 1)
            sum += __shfl_xor_sync(0xffffffffu, sum, s);
        g_Q[idx] = __fdividef(e, sum * a);
    }
}

// ============================================================
// state scan (NCH=64 chunks of 64)
// ============================================================
__global__ __launch_bounds__(128) void state_p1()
{
    int chunk = blockIdx.x, h = blockIdx.y, b = blockIdx.z;
    int tid = threadIdx.x;
    int l = tid >> 3, d0 = (tid & 7) * 8;
    __shared__ float ke_s[16][16];
    __shared__ float v_s[16][64];
    float acc[8] = {0, 0, 0, 0, 0, 0, 0, 0};
    int t0 = chunk * CSZ;
    for (int tt = 0; tt < CSZ; tt += 16) {
#pragma unroll
        for (int r = 0; r < 2; r++) {
            int f = r * 128 + tid, tr = f >> 4, li = f & 15;
            ke_s[tr][li] = g_K[(b * T_ + t0 + tt + tr) * L_ + h * LH + li];
        }
#pragma unroll
        for (int r = 0; r < 2; r++) {
            int f = r * 128 + tid, tr = f >> 4, dq = f & 15;
            *(float4*)&v_s[tr][dq * 4] =
                *(const float4*)&g_V[(b * T_ + t0 + tt + tr) * D_ + h * DH + dq * 4];
        }
        __syncthreads();
#pragma unroll
        for (int k = 0; k < 16; k++) {
            float kl = ke_s[k][l];
            float4 va = *(const float4*)&v_s[k][d0];
            float4 vb = *(const float4*)&v_s[k][d0 + 4];
            acc[0] = fmaf(kl, va.x, acc[0]); acc[1] = fmaf(kl, va.y, acc[1]);
            acc[2] = fmaf(kl, va.z, acc[2]); acc[3] = fmaf(kl, va.w, acc[3]);
            acc[4] = fmaf(kl, vb.x, acc[4]); acc[5] = fmaf(kl, vb.y, acc[5]);
            acc[6] = fmaf(kl, vb.z, acc[6]); acc[7] = fmaf(kl, vb.w, acc[7]);
        }
        __syncthreads();
    }
    float* Sp = &g_S[(((b * H_ + h) * NCH + chunk) * LH + l) * DH + d0];
    *(float4*)Sp       = make_float4(acc[0], acc[1], acc[2], acc[3]);
    *(float4*)(Sp + 4) = make_float4(acc[4], acc[5], acc[6], acc[7]);
}
__global__ void state_p2()
{
    int bh = blockIdx.x, tid = threadIdx.x;
    float4 run = make_float4(0, 0, 0, 0);
    for (int c = 0; c < NCH; c++) {
        float4* p = (float4*)&g_S[(size_t)(bh * NCH + c) * (LH * DH) + tid * 4];
        float4 v = *p;
        *p = run;
        run.x += v.x; run.y += v.y; run.z += v.z; run.w += v.w;
    }
}
__global__ __launch_bounds__(64) void scan_p3()
{
    int chunk = blockIdx.x, h = blockIdx.y, b = blockIdx.z;
    int tid = threadIdx.x;
    __shared__ float ke_s[16][16];
    __shared__ float w_s[16][16];
    __shared__ float v_s[16][64];
    float carry[16];
    const float* Sp = &g_S[(size_t)((b * H_ + h) * NCH + chunk) * (LH * DH)];
#pragma unroll
    for (int l = 0; l < 16; l++) carry[l] = Sp[l * 64 + tid];
    int t0 = chunk * CSZ;

    for (int tt = 0; tt < CSZ; tt += 16) {
#pragma unroll
        for (int r = 0; r < 4; r++) {
            int f = r * 64 + tid, tr = f >> 4, li = f & 15;
            int src = (b * T_ + t0 + tt + tr) * L_ + h * LH + li;
            ke_s[tr][li] = g_K[src];
            w_s[tr][li]  = g_Q[src];
        }
#pragma unroll
        for (int r = 0; r < 4; r++) {
            int f = r * 64 + tid, tr = f >> 4, dq = f & 15;
            *(float4*)&v_s[tr][dq * 4] =
                *(const float4*)&g_V[(b * T_ + t0 + tt + tr) * D_ + h * DH + dq * 4];
        }
        __syncthreads();
#pragma unroll
        for (int k = 0; k < 16; k++) {
            float v = v_s[k][tid];
            float4 ke0 = *(const float4*)&ke_s[k][0];
            float4 ke1 = *(const float4*)&ke_s[k][4];
            float4 ke2 = *(const float4*)&ke_s[k][8];
            float4 ke3 = *(const float4*)&ke_s[k][12];
            float4 w0 = *(const float4*)&w_s[k][0];
            float4 w1 = *(const float4*)&w_s[k][4];
            float4 w2 = *(const float4*)&w_s[k][8];
            float4 w3 = *(const float4*)&w_s[k][12];
            float y = 0.f;
            carry[0]  = fmaf(ke0.x, v, carry[0]);  y = fmaf(w0.x, carry[0],  y);
            carry[1]  = fmaf(ke0.y, v, carry[1]);  y = fmaf(w0.y, carry[1],  y);
            carry[2]  = fmaf(ke0.z, v, carry[2]);  y = fmaf(w0.z, carry[2],  y);
            carry[3]  = fmaf(ke0.w, v, carry[3]);  y = fmaf(w0.w, carry[3],  y);
            carry[4]  = fmaf(ke1.x, v, carry[4]);  y = fmaf(w1.x, carry[4],  y);
            carry[5]  = fmaf(ke1.y, v, carry[5]);  y = fmaf(w1.y, carry[5],  y);
            carry[6]  = fmaf(ke1.z, v, carry[6]);  y = fmaf(w1.z, carry[6],  y);
            carry[7]  = fmaf(ke1.w, v, carry[7]);  y = fmaf(w1.w, carry[7],  y);
            carry[8]  = fmaf(ke2.x, v, carry[8]);  y = fmaf(w2.x, carry[8],  y);
            carry[9]  = fmaf(ke2.y, v, carry[9]);  y = fmaf(w2.y, carry[9],  y);
            carry[10] = fmaf(ke2.z, v, carry[10]); y = fmaf(w2.z, carry[10], y);
            carry[11] = fmaf(ke2.w, v, carry[11]); y = fmaf(w2.w, carry[11], y);
            carry[12] = fmaf(ke3.x, v, carry[12]); y = fmaf(w3.x, carry[12], y);
            carry[13] = fmaf(ke3.y, v, carry[13]); y = fmaf(w3.y, carry[13], y);
            carry[14] = fmaf(ke3.z, v, carry[14]); y = fmaf(w3.z, carry[14], y);
            carry[15] = fmaf(ke3.w, v, carry[15]); y = fmaf(w3.w, carry[15], y);
            g_yh[(b * T_ + t0 + tt + k) * D_ + h * DH + tid] =
                __half_as_ushort(__float2half(y));
        }
        __syncthreads();
    }
}

// ============================================================
// permutation (fp16 shuffle)
// ============================================================
__global__ __launch_bounds__(256) void transpose_k()
{
    int t8 = blockIdx.x, b = blockIdx.y;
    int tid = threadIdx.x;
    __shared__ unsigned short ys[8][512];
#pragma unroll
    for (int r = 0; r < 2; r++) {
        int f = r * 256 + tid, tr = f >> 6, c8 = f & 63;
        *(uint4*)&ys[tr][c8 * 8] =
            *(const uint4*)&g_yh[(size_t)(b * T_ + t8 * 8 + tr) * D_ + c8 * 8];
    }
    __syncthreads();
#pragma unroll
    for (int r = 0; r < 2; r++) {
        int p = r * 256 + tid;
        int k = p >> 6, dh = p & 63;
        unsigned short v[8];
#pragma unroll
        for (int hh = 0; hh < 8; hh++) v[hh] = ys[k][hh * 64 + dh];
        int bp = dh >> 3, e = dh & 7;
        size_t didx = (size_t)bp * (T_ * D_) + (size_t)(e * 512 + t8) * D_ + k * 64 + b * 8;
        *(uint4*)(g_Yph + didx) = *(uint4*)v;
    }
}

// ============================================================
extern "C" void kernel_launch(void* const* d_in, const int* in_sizes, int n_in,
                              void* d_out, int out_size)
{
    const float* X  = (const float*)d_in[0];
    const float* Wk = (const float*)d_in[1];
    const float* Wq = (const float*)d_in[2];
    const float* Wv = (const float*)d_in[3];
    const float* Wo = (const float*)d_in[4];
    float* out = (float*)d_out;

    unsigned short *pXh, *pYph, *pWqkvh, *pWqkvl, *pWoh, *pWol;
    cudaGetSymbolAddress((void**)&pXh, g_Xh);
    cudaGetSymbolAddress((void**)&pYph, g_Yph);
    cudaGetSymbolAddress((void**)&pWqkvh, g_Wqkvh);
    cudaGetSymbolAddress((void**)&pWqkvl, g_Wqkvl);
    cudaGetSymbolAddress((void**)&pWoh, g_Woh);
    cudaGetSymbolAddress((void**)&pWol, g_Wol);

    cudaFuncSetAttribute(gemm_mma<0>, cudaFuncAttributeMaxDynamicSharedMemorySize, GEMM_SMEM);
    cudaFuncSetAttribute(gemm_mma<1>, cudaFuncAttributeMaxDynamicSharedMemorySize, GEMM_SMEM);

    // conversions
    conv_X<<<M_ * D_ / 1024, 256>>>(X);
    conv_W_all<<<dim3(16, 16, 4), 256>>>(Wq, Wk, Wv, Wo);

    // fused QKV projection (Q,K 1-term; V 2-term)
    gemm_mma<1><<<dim3(6, 256), 256, GEMM_SMEM>>>(pXh, pWqkvh, pWqkvl, nullptr);

    // alpha cumsum + fused softmax/normalize (128 chunks)
    alpha_p1<<<dim3(NCA, B_), 128>>>();
    alpha_p2<<<B_, 128>>>();
    alpha_p3<<<dim3(NCA, B_), 128>>>();

    // chunk-parallel state scan (64 chunks)
    state_p1<<<dim3(NCH, H_, B_), 128>>>();
    state_p2<<<B_ * H_, 256>>>();
    scan_p3<<<dim3(NCH, H_, B_), 64>>>();

    // permutation + O projection (2-term)
    transpose_k<<<dim3(T_ / 8, B_), 256>>>();
    gemm_mma<0><<<dim3(4, 256), 256, GEMM_SMEM>>>(pYph, pWoh, pWol, out);
}

// round 9
// speedup vs baseline: 2.7122x; 1.0036x over previous
#include <cuda_runtime.h>
#include <cuda_fp16.h>
#include <cstdint>

#define T_  4096
#define B_  8
#define D_  512
#define L_  128
#define H_  8
#define DH  64
#define LH  16
#define M_  (B_*T_)
#define NCH 64          // state-scan chunks
#define CSZ 64          // T_/NCH
#define NCA 128         // alpha chunks
#define CSA 32          // T_/NCA

// ---------------- scratch ----------------
__device__ float g_Q[M_*L_];
__device__ float g_K[M_*L_];
__device__ float g_V[M_*D_];
__device__ float g_csum[B_*NCA*L_];
__device__ float g_S[B_*H_*NCH*LH*DH];
__device__ unsigned short g_Xh[M_*D_];       // X fp16
__device__ unsigned short g_yh[M_*D_];       // scan out fp16 natural
__device__ unsigned short g_Yph[M_*D_];      // permuted fp16
__device__ unsigned short g_Wqkvh[(2*L_+D_)*D_], g_Wqkvl[(2*L_+D_)*D_];
__device__ unsigned short g_Woh[D_*D_], g_Wol[D_*D_];

// ---------------- PTX helpers ----------------
__device__ __forceinline__ uint32_t smem_u32(const void* p) {
    uint32_t a;
    asm("{ .reg .u64 t; cvta.to.shared.u64 t, %1; cvt.u32.u64 %0, t; }" : "=r"(a) : "l"(p));
    return a;
}
__device__ __forceinline__ void ldsm4(uint32_t* r, uint32_t addr) {
    asm volatile("ldmatrix.sync.aligned.m8n8.x4.shared.b16 {%0,%1,%2,%3}, [%4];"
                 : "=r"(r[0]), "=r"(r[1]), "=r"(r[2]), "=r"(r[3]) : "r"(addr));
}
__device__ __forceinline__ void mma16816(float* d, const uint32_t* a, const uint32_t* b) {
    asm volatile("mma.sync.aligned.m16n8k16.row.col.f32.f16.f16.f32 "
                 "{%0,%1,%2,%3}, {%4,%5,%6,%7}, {%8,%9}, {%0,%1,%2,%3};"
                 : "+f"(d[0]), "+f"(d[1]), "+f"(d[2]), "+f"(d[3])
                 : "r"(a[0]), "r"(a[1]), "r"(a[2]), "r"(a[3]), "r"(b[0]), "r"(b[1]));
}
#define CP_ASYNC16(dst, src) \
    asm volatile("cp.async.cg.shared.global [%0], [%1], 16;" :: "r"(dst), "l"(src))
#define CP_COMMIT() asm volatile("cp.async.commit_group;" ::: "memory")
#define CP_WAIT(n)  asm volatile("cp.async.wait_group %0;" :: "n"(n) : "memory")

// ============================================================
// fp16 GEMM via mma.sync, fp32 acc. Tile 128x128, BK=32, 256 thr.
// B-term count is runtime per-CTA: MODE 1, blockIdx.x<2 (Q,K) -> 1-term.
// MODE 1: fused QKV epi (bx0 Q raw, bx1 K exp(0.125*), bx>=2 V)
// MODE 0: C[M,512] (O projection), always 2-term.
// ============================================================
#define ROWB 80
#define MATB (128 * ROWB)
#define BUFB (3 * MATB)
#define GEMM_SMEM (2 * BUFB)

__device__ __forceinline__ void issue_loads(const unsigned short* ah,
                                            const unsigned short* bh,
                                            const unsigned short* bl,
                                            int k0, uint32_t smbuf, int tid, bool bl_on)
{
#pragma unroll
    for (int half = 0; half < 2; half++) {
        int c = half * 256 + tid;
        int r = c >> 2, s = c & 3;
        uint32_t soff = (uint32_t)(r * ROWB + s * 16);
        CP_ASYNC16(smbuf + 0 * MATB + soff, ah + (size_t)r * 512 + k0 + s * 8);
        CP_ASYNC16(smbuf + 1 * MATB + soff, bh + (size_t)r * 512 + k0 + s * 8);
        if (bl_on)
            CP_ASYNC16(smbuf + 2 * MATB + soff, bl + (size_t)r * 512 + k0 + s * 8);
    }
}

template<int MODE>
__global__ __launch_bounds__(256, 2) void gemm_mma(const unsigned short* __restrict__ Ah,
                                                   const unsigned short* __restrict__ Bh,
                                                   const unsigned short* __restrict__ Bl,
                                                   float* __restrict__ C)
{
    extern __shared__ char sm[];
    const int tid = threadIdx.x;
    const int wid = tid >> 5, lane = tid & 31;
    const int wm = wid >> 2, wn = wid & 3;
    const int m0 = blockIdx.y * 128;
    const int n0 = blockIdx.x * 128;
    const uint32_t smb = smem_u32(sm);
    const bool two = (MODE == 0) || (blockIdx.x >= 2);

    const unsigned short* ah = Ah + (size_t)m0 * 512;
    const unsigned short* bh = Bh + (size_t)n0 * 512;
    const unsigned short* bl = Bl + (size_t)n0 * 512;

    float acc[4][4][4];
#pragma unroll
    for (int i = 0; i < 4; i++)
#pragma unroll
        for (int j = 0; j < 4; j++)
#pragma unroll
            for (int e = 0; e < 4; e++) acc[i][j][e] = 0.f;

    const uint32_t a_lane = (uint32_t)((wm * 64 + (lane & 15)) * ROWB + (lane >> 4) * 16);
    const uint32_t b_lane = (uint32_t)((wn * 32 + (lane & 15)) * ROWB + (lane >> 4) * 16);

    issue_loads(ah, bh, bl, 0, smb, tid, two);
    CP_COMMIT();

    const int NIT = 512 / 32;
    for (int ki = 0; ki < NIT; ki++) {
        const uint32_t buf = smb + (uint32_t)(ki & 1) * BUFB;
        if (ki + 1 < NIT) {
            issue_loads(ah, bh, bl, (ki + 1) * 32, smb + (uint32_t)((ki + 1) & 1) * BUFB, tid, two);
            CP_COMMIT();
            CP_WAIT(1);
        } else {
            CP_WAIT(0);
        }
        __syncthreads();

#pragma unroll
        for (int ks = 0; ks < 2; ks++) {
            const uint32_t koff = (uint32_t)(ks * 32);
            uint32_t fBh[4][2], fBl[4][2];
#pragma unroll
            for (int p = 0; p < 2; p++) {
                uint32_t r[4];
                ldsm4(r, buf + 1 * MATB + b_lane + (uint32_t)(p * 16 * ROWB) + koff);
                fBh[2 * p][0] = r[0]; fBh[2 * p][1] = r[2];
                fBh[2 * p + 1][0] = r[1]; fBh[2 * p + 1][1] = r[3];
                if (two) {
                    ldsm4(r, buf + 2 * MATB + b_lane + (uint32_t)(p * 16 * ROWB) + koff);
                    fBl[2 * p][0] = r[0]; fBl[2 * p][1] = r[2];
                    fBl[2 * p + 1][0] = r[1]; fBl[2 * p + 1][1] = r[3];
                }
            }
#pragma unroll
            for (int mf = 0; mf < 4; mf++) {
                uint32_t fAh[4];
                ldsm4(fAh, buf + 0 * MATB + a_lane + (uint32_t)(mf * 16 * ROWB) + koff);
#pragma unroll
                for (int nf = 0; nf < 4; nf++) {
                    mma16816(acc[mf][nf], fAh, fBh[nf]);
                    if (two) mma16816(acc[mf][nf], fAh, fBl[nf]);
                }
            }
        }
        __syncthreads();
    }

    // epilogue
    const int rr = lane >> 2, cc = (lane & 3) * 2;
    float* Cout;
    int cstride, colbase;
    bool do_exp = false;
    if (MODE == 1) {
        if (blockIdx.x == 0)      { Cout = g_Q; cstride = L_; colbase = 0; }
        else if (blockIdx.x == 1) { Cout = g_K; cstride = L_; colbase = 0; do_exp = true; }
        else                      { Cout = g_V; cstride = D_; colbase = (blockIdx.x - 2) * 128; }
    } else {
        Cout = C; cstride = D_; colbase = n0;
    }
#pragma unroll
    for (int mf = 0; mf < 4; mf++) {
#pragma unroll
        for (int nf = 0; nf < 4; nf++) {
            int row = m0 + wm * 64 + mf * 16 + rr;
            int col = colbase + wn * 32 + nf * 8 + cc;
            float d0 = acc[mf][nf][0], d1 = acc[mf][nf][1];
            float d2 = acc[mf][nf][2], d3 = acc[mf][nf][3];
            if (MODE == 1 && do_exp) {
                d0 = __expf(0.125f * d0); d1 = __expf(0.125f * d1);
                d2 = __expf(0.125f * d2); d3 = __expf(0.125f * d3);
            }
            *(float2*)(Cout + (size_t)row * cstride + col)       = make_float2(d0, d1);
            *(float2*)(Cout + (size_t)(row + 8) * cstride + col) = make_float2(d2, d3);
        }
    }
}

// ============================================================
// conversions
// ============================================================
__device__ __forceinline__ void split2h(float x, unsigned short& h, unsigned short& l) {
    __half hb = __float2half(x);
    __half lb = __float2half(x - __half2float(hb));
    h = __half_as_ushort(hb);
    l = __half_as_ushort(lb);
}
__global__ void conv_X(const float* __restrict__ X)
{
    int i = blockIdx.x * 256 + threadIdx.x;
    float4 v = ((const float4*)X)[i];
    ushort4 h;
    h.x = __half_as_ushort(__float2half(v.x));
    h.y = __half_as_ushort(__float2half(v.y));
    h.z = __half_as_ushort(__float2half(v.z));
    h.w = __half_as_ushort(__float2half(v.w));
    ((ushort4*)g_Xh)[i] = h;
}
// all four W[512][N] -> [N][512] hi/lo transposes in one launch, tiled
__global__ __launch_bounds__(256) void conv_W_all(const float* __restrict__ Wq,
                                                  const float* __restrict__ Wk,
                                                  const float* __restrict__ Wv,
                                                  const float* __restrict__ Wo)
{
    __shared__ float ts[32][33];
    const int z = blockIdx.z;
    const float* W;
    unsigned short *Th, *Tl;
    int N, roff;
    if (z == 0)      { W = Wq; Th = g_Wqkvh; Tl = g_Wqkvl; N = L_;  roff = 0; }
    else if (z == 1) { W = Wk; Th = g_Wqkvh; Tl = g_Wqkvl; N = L_;  roff = L_; }
    else if (z == 2) { W = Wv; Th = g_Wqkvh; Tl = g_Wqkvl; N = D_;  roff = 2 * L_; }
    else             { W = Wo; Th = g_Woh;   Tl = g_Wol;   N = D_;  roff = 0; }
    const int n0 = blockIdx.x * 32, k0 = blockIdx.y * 32;
    if (n0 >= N) return;
    const int tid = threadIdx.x;
#pragma unroll
    for (int i = 0; i < 4; i++) {
        int f = i * 256 + tid;
        int kk = f >> 5, nn = f & 31;
        ts[kk][nn] = W[(size_t)(k0 + kk) * N + n0 + nn];
    }
    __syncthreads();
#pragma unroll
    for (int i = 0; i < 4; i++) {
        int f = i * 256 + tid;
        int nn = f >> 5, kk = f & 31;
        unsigned short h, l;
        split2h(ts[kk][nn], h, l);
        size_t di = (size_t)(roff + n0 + nn) * 512 + k0 + kk;
        Th[di] = h;
        Tl[di] = l;
    }
}

// ============================================================
// alpha cumsum (NCA=128 chunks); p3 fuses softmax + normalize
// ============================================================
__global__ void alpha_p1()
{
    int chunk = blockIdx.x, b = blockIdx.y, l = threadIdx.x;
    float s = 0.f;
    int base = (b * T_ + chunk * CSA) * L_ + l;
    for (int i = 0; i < CSA; i++) s += g_K[base + i * L_];
    g_csum[(b * NCA + chunk) * L_ + l] = s;
}
__global__ void alpha_p2()
{
    int b = blockIdx.x, l = threadIdx.x;
    float run = 0.f;
    for (int c = 0; c < NCA; c++) {
        int idx = (b * NCA + c) * L_ + l;
        float v = g_csum[idx];
        g_csum[idx] = run;
        run += v;
    }
}
__global__ void alpha_p3()
{
    int chunk = blockIdx.x, b = blockIdx.y, l = threadIdx.x;
    float a = g_csum[(b * NCA + chunk) * L_ + l];
    int base = (b * T_ + chunk * CSA) * L_ + l;
    for (int i = 0; i < CSA; i++) {
        int idx = base + i * L_;
        a += g_K[idx];
        float q = g_Q[idx] * 0.125f;
        float m = q;
#pragma unroll
        for (int s = 8; s >= 1; s >>= 1)
            m = fmaxf(m, __shfl_xor_sync(0xffffffffu, m, s));
        float e = __expf(q - m);
        float sum = e;
#pragma unroll
        for (int s = 8; s >= 1; s >>= 1)
            sum += __shfl_xor_sync(0xffffffffu, sum, s);
        g_Q[idx] = __fdividef(e, sum * a);
    }
}

// ============================================================
// state scan (NCH=64 chunks of 64)
// ============================================================
__global__ __launch_bounds__(128) void state_p1()
{
    int chunk = blockIdx.x, h = blockIdx.y, b = blockIdx.z;
    int tid = threadIdx.x;
    int l = tid >> 3, d0 = (tid & 7) * 8;
    __shared__ float ke_s[16][16];
    __shared__ float v_s[16][64];
    float acc[8] = {0, 0, 0, 0, 0, 0, 0, 0};
    int t0 = chunk * CSZ;
    for (int tt = 0; tt < CSZ; tt += 16) {
#pragma unroll
        for (int r = 0; r < 2; r++) {
            int f = r * 128 + tid, tr = f >> 4, li = f & 15;
            ke_s[tr][li] = g_K[(b * T_ + t0 + tt + tr) * L_ + h * LH + li];
        }
#pragma unroll
        for (int r = 0; r < 2; r++) {
            int f = r * 128 + tid, tr = f >> 4, dq = f & 15;
            *(float4*)&v_s[tr][dq * 4] =
                *(const float4*)&g_V[(b * T_ + t0 + tt + tr) * D_ + h * DH + dq * 4];
        }
        __syncthreads();
#pragma unroll
        for (int k = 0; k < 16; k++) {
            float kl = ke_s[k][l];
            float4 va = *(const float4*)&v_s[k][d0];
            float4 vb = *(const float4*)&v_s[k][d0 + 4];
            acc[0] = fmaf(kl, va.x, acc[0]); acc[1] = fmaf(kl, va.y, acc[1]);
            acc[2] = fmaf(kl, va.z, acc[2]); acc[3] = fmaf(kl, va.w, acc[3]);
            acc[4] = fmaf(kl, vb.x, acc[4]); acc[5] = fmaf(kl, vb.y, acc[5]);
            acc[6] = fmaf(kl, vb.z, acc[6]); acc[7] = fmaf(kl, vb.w, acc[7]);
        }
        __syncthreads();
    }
    float* Sp = &g_S[(((b * H_ + h) * NCH + chunk) * LH + l) * DH + d0];
    *(float4*)Sp       = make_float4(acc[0], acc[1], acc[2], acc[3]);
    *(float4*)(Sp + 4) = make_float4(acc[4], acc[5], acc[6], acc[7]);
}
__global__ void state_p2()
{
    int bh = blockIdx.x, tid = threadIdx.x;
    float4 run = make_float4(0, 0, 0, 0);
    for (int c = 0; c < NCH; c++) {
        float4* p = (float4*)&g_S[(size_t)(bh * NCH + c) * (LH * DH) + tid * 4];
        float4 v = *p;
        *p = run;
        run.x += v.x; run.y += v.y; run.z += v.z; run.w += v.w;
    }
}
__global__ __launch_bounds__(64) void scan_p3()
{
    int chunk = blockIdx.x, h = blockIdx.y, b = blockIdx.z;
    int tid = threadIdx.x;
    __shared__ float ke_s[16][16];
    __shared__ float w_s[16][16];
    __shared__ float v_s[16][64];
    float carry[16];
    const float* Sp = &g_S[(size_t)((b * H_ + h) * NCH + chunk) * (LH * DH)];
#pragma unroll
    for (int l = 0; l < 16; l++) carry[l] = Sp[l * 64 + tid];
    int t0 = chunk * CSZ;

    for (int tt = 0; tt < CSZ; tt += 16) {
#pragma unroll
        for (int r = 0; r < 4; r++) {
            int f = r * 64 + tid, tr = f >> 4, li = f & 15;
            int src = (b * T_ + t0 + tt + tr) * L_ + h * LH + li;
            ke_s[tr][li] = g_K[src];
            w_s[tr][li]  = g_Q[src];
        }
#pragma unroll
        for (int r = 0; r < 4; r++) {
            int f = r * 64 + tid, tr = f >> 4, dq = f & 15;
            *(float4*)&v_s[tr][dq * 4] =
                *(const float4*)&g_V[(b * T_ + t0 + tt + tr) * D_ + h * DH + dq * 4];
        }
        __syncthreads();
#pragma unroll
        for (int k = 0; k < 16; k++) {
            float v = v_s[k][tid];
            float4 ke0 = *(const float4*)&ke_s[k][0];
            float4 ke1 = *(const float4*)&ke_s[k][4];
            float4 ke2 = *(const float4*)&ke_s[k][8];
            float4 ke3 = *(const float4*)&ke_s[k][12];
            float4 w0 = *(const float4*)&w_s[k][0];
            float4 w1 = *(const float4*)&w_s[k][4];
            float4 w2 = *(const float4*)&w_s[k][8];
            float4 w3 = *(const float4*)&w_s[k][12];
            float y = 0.f;
            carry[0]  = fmaf(ke0.x, v, carry[0]);  y = fmaf(w0.x, carry[0],  y);
            carry[1]  = fmaf(ke0.y, v, carry[1]);  y = fmaf(w0.y, carry[1],  y);
            carry[2]  = fmaf(ke0.z, v, carry[2]);  y = fmaf(w0.z, carry[2],  y);
            carry[3]  = fmaf(ke0.w, v, carry[3]);  y = fmaf(w0.w, carry[3],  y);
            carry[4]  = fmaf(ke1.x, v, carry[4]);  y = fmaf(w1.x, carry[4],  y);
            carry[5]  = fmaf(ke1.y, v, carry[5]);  y = fmaf(w1.y, carry[5],  y);
            carry[6]  = fmaf(ke1.z, v, carry[6]);  y = fmaf(w1.z, carry[6],  y);
            carry[7]  = fmaf(ke1.w, v, carry[7]);  y = fmaf(w1.w, carry[7],  y);
            carry[8]  = fmaf(ke2.x, v, carry[8]);  y = fmaf(w2.x, carry[8],  y);
            carry[9]  = fmaf(ke2.y, v, carry[9]);  y = fmaf(w2.y, carry[9],  y);
            carry[10] = fmaf(ke2.z, v, carry[10]); y = fmaf(w2.z, carry[10], y);
            carry[11] = fmaf(ke2.w, v, carry[11]); y = fmaf(w2.w, carry[11], y);
            carry[12] = fmaf(ke3.x, v, carry[12]); y = fmaf(w3.x, carry[12], y);
            carry[13] = fmaf(ke3.y, v, carry[13]); y = fmaf(w3.y, carry[13], y);
            carry[14] = fmaf(ke3.z, v, carry[14]); y = fmaf(w3.z, carry[14], y);
            carry[15] = fmaf(ke3.w, v, carry[15]); y = fmaf(w3.w, carry[15], y);
            g_yh[(b * T_ + t0 + tt + k) * D_ + h * DH + tid] =
                __half_as_ushort(__float2half(y));
        }
        __syncthreads();
    }
}

// ============================================================
// permutation (fp16 shuffle)
// ============================================================
__global__ __launch_bounds__(256) void transpose_k()
{
    int t8 = blockIdx.x, b = blockIdx.y;
    int tid = threadIdx.x;
    __shared__ unsigned short ys[8][512];
#pragma unroll
    for (int r = 0; r < 2; r++) {
        int f = r * 256 + tid, tr = f >> 6, c8 = f & 63;
        *(uint4*)&ys[tr][c8 * 8] =
            *(const uint4*)&g_yh[(size_t)(b * T_ + t8 * 8 + tr) * D_ + c8 * 8];
    }
    __syncthreads();
#pragma unroll
    for (int r = 0; r < 2; r++) {
        int p = r * 256 + tid;
        int k = p >> 6, dh = p & 63;
        unsigned short v[8];
#pragma unroll
        for (int hh = 0; hh < 8; hh++) v[hh] = ys[k][hh * 64 + dh];
        int bp = dh >> 3, e = dh & 7;
        size_t didx = (size_t)bp * (T_ * D_) + (size_t)(e * 512 + t8) * D_ + k * 64 + b * 8;
        *(uint4*)(g_Yph + didx) = *(uint4*)v;
    }
}

// ============================================================
extern "C" void kernel_launch(void* const* d_in, const int* in_sizes, int n_in,
                              void* d_out, int out_size)
{
    const float* X  = (const float*)d_in[0];
    const float* Wk = (const float*)d_in[1];
    const float* Wq = (const float*)d_in[2];
    const float* Wv = (const float*)d_in[3];
    const float* Wo = (const float*)d_in[4];
    float* out = (float*)d_out;

    unsigned short *pXh, *pYph, *pWqkvh, *pWqkvl, *pWoh, *pWol;
    cudaGetSymbolAddress((void**)&pXh, g_Xh);
    cudaGetSymbolAddress((void**)&pYph, g_Yph);
    cudaGetSymbolAddress((void**)&pWqkvh, g_Wqkvh);
    cudaGetSymbolAddress((void**)&pWqkvl, g_Wqkvl);
    cudaGetSymbolAddress((void**)&pWoh, g_Woh);
    cudaGetSymbolAddress((void**)&pWol, g_Wol);

    cudaFuncSetAttribute(gemm_mma<0>, cudaFuncAttributeMaxDynamicSharedMemorySize, GEMM_SMEM);
    cudaFuncSetAttribute(gemm_mma<1>, cudaFuncAttributeMaxDynamicSharedMemorySize, GEMM_SMEM);

    // conversions
    conv_X<<<M_ * D_ / 1024, 256>>>(X);
    conv_W_all<<<dim3(16, 16, 4), 256>>>(Wq, Wk, Wv, Wo);

    // fused QKV projection (Q,K 1-term; V 2-term)
    gemm_mma<1><<<dim3(6, 256), 256, GEMM_SMEM>>>(pXh, pWqkvh, pWqkvl, nullptr);

    // alpha cumsum + fused softmax/normalize (128 chunks)
    alpha_p1<<<dim3(NCA, B_), 128>>>();
    alpha_p2<<<B_, 128>>>();
    alpha_p3<<<dim3(NCA, B_), 128>>>();

    // chunk-parallel state scan (64 chunks)
    state_p1<<<dim3(NCH, H_, B_), 128>>>();
    state_p2<<<B_ * H_, 256>>>();
    scan_p3<<<dim3(NCH, H_, B_), 64>>>();

    // permutation + O projection (2-term)
    transpose_k<<<dim3(T_ / 8, B_), 256>>>();
    gemm_mma<0><<<dim3(4, 256), 256, GEMM_SMEM>>>(pYph, pWoh, pWol, out);
}